// round 5
// baseline (speedup 1.0000x reference)
#include <cuda_runtime.h>
#include <cuda_bf16.h>
#include <cstdint>
#include <cstddef>

#define BB 8
#define SS 2048
#define DD 1024
#define ND 3072   // merged QKV output width

typedef __nv_bfloat16 bf16;

// ---------------- scratch ----------------
__device__ bf16 g_xh[(size_t)BB * SS * DD];
__device__ bf16 g_xl[(size_t)BB * SS * DD];
__device__ bf16 g_Wth[(size_t)ND * DD];          // [3072][1024] K-major (pre-transposed)
__device__ bf16 g_Wtl[(size_t)ND * DD];
__device__ float g_bias[ND];
__device__ bf16 g_QKVh[(size_t)BB * SS * ND];    // [16384][3072]
__device__ bf16 g_QKVl[(size_t)BB * SS * ND];
__device__ bf16 g_Vth[(size_t)BB * DD * SS];     // [b][d][s]
__device__ bf16 g_Vtl[(size_t)BB * DD * SS];
__device__ float g_S[(size_t)BB * SS * SS];
__device__ bf16 g_Ph[(size_t)BB * SS * SS];
__device__ bf16 g_Pl[(size_t)BB * SS * SS];

// ---------------- PTX helpers ----------------
__device__ __forceinline__ uint32_t smem_u32(const void* p) {
    uint32_t a;
    asm("{ .reg .u64 t; cvta.to.shared.u64 t, %1; cvt.u32.u64 %0, t; }" : "=r"(a) : "l"(p));
    return a;
}
__device__ __forceinline__ void cp16(uint32_t s, const void* g) {
    asm volatile("cp.async.cg.shared.global [%0], [%1], 16;\n" :: "r"(s), "l"(g));
}
__device__ __forceinline__ void cp_commit() { asm volatile("cp.async.commit_group;\n" ::: "memory"); }
template <int N> __device__ __forceinline__ void cp_wait() {
    asm volatile("cp.async.wait_group %0;\n" :: "n"(N) : "memory");
}
__device__ __forceinline__ void ldsm_x4(uint32_t& r0, uint32_t& r1, uint32_t& r2, uint32_t& r3, uint32_t a) {
    asm volatile("ldmatrix.sync.aligned.m8n8.x4.shared.b16 {%0,%1,%2,%3}, [%4];"
                 : "=r"(r0), "=r"(r1), "=r"(r2), "=r"(r3) : "r"(a));
}
__device__ __forceinline__ void mma16816(float* d,
                                         uint32_t a0, uint32_t a1, uint32_t a2, uint32_t a3,
                                         uint32_t b0, uint32_t b1) {
    asm volatile("mma.sync.aligned.m16n8k16.row.col.f32.bf16.bf16.f32 "
                 "{%0,%1,%2,%3}, {%4,%5,%6,%7}, {%8,%9}, {%0,%1,%2,%3};"
                 : "+f"(d[0]), "+f"(d[1]), "+f"(d[2]), "+f"(d[3])
                 : "r"(a0), "r"(a1), "r"(a2), "r"(a3), "r"(b0), "r"(b1));
}

#define SW128(o) ((o) ^ (((o) >> 3) & 0x70))

// smem stage: A(128 rows) hi+lo = 32KB, B(256 rows) hi+lo = 64KB
static constexpr int S_AH = 0, S_AL = 16384, S_BH = 32768, S_BL = 65536;
static constexpr int STAGE = 98304;              // 96 KB
static constexpr int STAGES = 2;
static constexpr int SMEM_TOTAL = STAGES * STAGE; // 192 KB

// ---------------- split-bf16 mma.sync GEMM, CTA 128x256, warp 64x64 ----------------
// C[M,N] = (Ah+Al)[M,K] x (Bh+Bl)[N,K]^T (3-pass compensated, fp32 accum)
// EPI: 0 = fp32 out, 1 = bf16 hi/lo split out
template <int EPI, bool HASB>
__global__ __launch_bounds__(256, 1)
void tc_gemm(const bf16* __restrict__ Ah_, const bf16* __restrict__ Al_,
             const bf16* __restrict__ Bh_, const bf16* __restrict__ Bl_,
             const float* __restrict__ bias,
             float* __restrict__ Co, bf16* __restrict__ Coh, bf16* __restrict__ Col,
             int Kd, int lda, int ldb,
             long long sA, long long sB, long long sC, int ldo, float scale)
{
    extern __shared__ char smem[];
    const uint32_t su = smem_u32(smem);
    const int tid = threadIdx.x, lane = tid & 31, wid = tid >> 5;
    const int wm = wid >> 2, wn = wid & 3;          // 2(m) x 4(n), warp tile 64x64
    const int rowBase = blockIdx.y * 128, colBase = blockIdx.x * 256;

    Ah_ += (long long)blockIdx.z * sA;  Al_ += (long long)blockIdx.z * sA;
    Bh_ += (long long)blockIdx.z * sB;  Bl_ += (long long)blockIdx.z * sB;
    if (EPI == 0) Co += (long long)blockIdx.z * sC;
    else { Coh += (long long)blockIdx.z * sC; Col += (long long)blockIdx.z * sC; }

    float acc[32][4] = {};                           // [im*8+in][4]

    const int NC = Kd >> 6;

    auto load_stage = [&](int s, int k0) {
        const uint32_t base = su + s * STAGE;
        #pragma unroll
        for (int j = 0; j < 4; ++j) {                // A: 128 rows
            const int idx = tid + j * 256, r = idx >> 3, cu = idx & 7;
            const size_t go = (size_t)(rowBase + r) * lda + k0 + cu * 8;
            const uint32_t so = SW128((uint32_t)(r * 128 + cu * 16));
            cp16(base + S_AH + so, Ah_ + go);
            cp16(base + S_AL + so, Al_ + go);
        }
        #pragma unroll
        for (int j = 0; j < 8; ++j) {                // B: 256 rows
            const int idx = tid + j * 256, r = idx >> 3, cu = idx & 7;
            const size_t go = (size_t)(colBase + r) * ldb + k0 + cu * 8;
            const uint32_t so = SW128((uint32_t)(r * 128 + cu * 16));
            cp16(base + S_BH + so, Bh_ + go);
            cp16(base + S_BL + so, Bl_ + go);
        }
        cp_commit();
    };

    load_stage(0, 0);

    const uint32_t sw   = (lane & 7) << 4;
    const uint32_t arow = (lane & 7) + (lane & 8);
    const uint32_t koff = (lane & 16);

    for (int c = 0; c < NC; ++c) {
        if (c + 1 < NC) load_stage((c + 1) & 1, (c + 1) << 6);
        else            cp_commit();
        cp_wait<1>();
        __syncthreads();

        const uint32_t base = su + (c & 1) * STAGE;
        #pragma unroll
        for (int ks = 0; ks < 4; ++ks) {
            uint32_t ah[4][4], al[4][4];
            #pragma unroll
            for (int im = 0; im < 4; ++im) {
                const uint32_t off = (wm * 64 + im * 16 + arow) * 128 + ks * 32 + koff;
                ldsm_x4(ah[im][0], ah[im][1], ah[im][2], ah[im][3], (base + S_AH + off) ^ sw);
                ldsm_x4(al[im][0], al[im][1], al[im][2], al[im][3], (base + S_AL + off) ^ sw);
            }
            uint32_t bf[4][4];
            #pragma unroll
            for (int ip = 0; ip < 4; ++ip) {         // B hi
                const uint32_t off = (wn * 64 + ip * 16 + arow) * 128 + ks * 32 + koff;
                ldsm_x4(bf[ip][0], bf[ip][1], bf[ip][2], bf[ip][3], (base + S_BH + off) ^ sw);
            }
            #pragma unroll
            for (int im = 0; im < 4; ++im)
                #pragma unroll
                for (int in = 0; in < 8; ++in) {
                    float* d = acc[im * 8 + in];
                    const int ip = in >> 1, sb = in & 1;
                    mma16816(d, ah[im][0], ah[im][1], ah[im][2], ah[im][3],
                             bf[ip][sb], bf[ip][2 + sb]);                       // hi*hi
                    mma16816(d, al[im][0], al[im][1], al[im][2], al[im][3],
                             bf[ip][sb], bf[ip][2 + sb]);                       // lo*hi
                }
            #pragma unroll
            for (int ip = 0; ip < 4; ++ip) {         // B lo (reuse regs)
                const uint32_t off = (wn * 64 + ip * 16 + arow) * 128 + ks * 32 + koff;
                ldsm_x4(bf[ip][0], bf[ip][1], bf[ip][2], bf[ip][3], (base + S_BL + off) ^ sw);
            }
            #pragma unroll
            for (int im = 0; im < 4; ++im)
                #pragma unroll
                for (int in = 0; in < 8; ++in) {
                    float* d = acc[im * 8 + in];
                    const int ip = in >> 1, sb = in & 1;
                    mma16816(d, ah[im][0], ah[im][1], ah[im][2], ah[im][3],
                             bf[ip][sb], bf[ip][2 + sb]);                       // hi*lo
                }
        }
        __syncthreads();
    }

    // ---------------- epilogue ----------------
    #pragma unroll
    for (int im = 0; im < 4; ++im) {
        #pragma unroll
        for (int in = 0; in < 8; ++in) {
            const float* d = acc[im * 8 + in];
            const int row0 = rowBase + wm * 64 + im * 16 + (lane >> 2);
            const int col0 = colBase + wn * 64 + in * 8 + 2 * (lane & 3);
            #pragma unroll
            for (int h = 0; h < 2; ++h) {
                const int row = row0 + h * 8;
                float v0 = d[2 * h + 0], v1 = d[2 * h + 1];
                if (HASB) { v0 += bias[col0]; v1 += bias[col0 + 1]; }
                v0 *= scale; v1 *= scale;
                if (EPI == 0) {
                    float2 f2; f2.x = v0; f2.y = v1;
                    *reinterpret_cast<float2*>(Co + (size_t)row * ldo + col0) = f2;
                } else {
                    const bf16 h0 = __float2bfloat16(v0), h1 = __float2bfloat16(v1);
                    __nv_bfloat162 H; H.x = h0; H.y = h1;
                    __nv_bfloat162 L;
                    L.x = __float2bfloat16(v0 - __bfloat162float(h0));
                    L.y = __float2bfloat16(v1 - __bfloat162float(h1));
                    *reinterpret_cast<__nv_bfloat162*>(Coh + (size_t)row * ldo + col0) = H;
                    *reinterpret_cast<__nv_bfloat162*>(Col + (size_t)row * ldo + col0) = L;
                }
            }
        }
    }
}

// ---------------- aux kernels ----------------
__global__ __launch_bounds__(256)
void split_x_kernel(const float4* __restrict__ src, bf16* __restrict__ hi, bf16* __restrict__ lo, int n4)
{
    const int i = blockIdx.x * 256 + threadIdx.x;
    if (i >= n4) return;
    const float4 v = src[i];
    bf16 h0 = __float2bfloat16(v.x), h1 = __float2bfloat16(v.y);
    bf16 h2 = __float2bfloat16(v.z), h3 = __float2bfloat16(v.w);
    __nv_bfloat162 H0; H0.x = h0; H0.y = h1;
    __nv_bfloat162 H1; H1.x = h2; H1.y = h3;
    __nv_bfloat162 L0, L1;
    L0.x = __float2bfloat16(v.x - __bfloat162float(h0));
    L0.y = __float2bfloat16(v.y - __bfloat162float(h1));
    L1.x = __float2bfloat16(v.z - __bfloat162float(h2));
    L1.y = __float2bfloat16(v.w - __bfloat162float(h3));
    reinterpret_cast<__nv_bfloat162*>(hi)[2 * i] = H0;
    reinterpret_cast<__nv_bfloat162*>(hi)[2 * i + 1] = H1;
    reinterpret_cast<__nv_bfloat162*>(lo)[2 * i] = L0;
    reinterpret_cast<__nv_bfloat162*>(lo)[2 * i + 1] = L1;
}

// W [1024][1024] -> Wt section [n][d] K-major split, written at Th/Tl (pre-offset)
__global__ __launch_bounds__(256)
void transpose_split_w(const float* __restrict__ W, bf16* __restrict__ Th, bf16* __restrict__ Tl)
{
    __shared__ float t[32][33];
    const int tx = threadIdx.x, ty = threadIdx.y;
    const int x0 = blockIdx.x * 32, y0 = blockIdx.y * 32;
    #pragma unroll
    for (int j = 0; j < 32; j += 8)
        t[ty + j][tx] = W[(size_t)(y0 + ty + j) * DD + x0 + tx];
    __syncthreads();
    #pragma unroll
    for (int j = 0; j < 32; j += 8) {
        const float v = t[tx][ty + j];
        const size_t addr = (size_t)(x0 + ty + j) * DD + y0 + tx;
        const bf16 h = __float2bfloat16(v);
        Th[addr] = h;
        Tl[addr] = __float2bfloat16(v - __bfloat162float(h));
    }
}

__global__ void concat_bias(const float* bq, const float* bk, const float* bv, float* o)
{
    const int i = blockIdx.x * 256 + threadIdx.x;
    if (i < DD) o[i] = bq[i];
    else if (i < 2 * DD) o[i] = bk[i - DD];
    else if (i < ND) o[i] = bv[i - 2 * DD];
}

// V slice of QKV [b*2048+s][3072] (cols 2048..3071) -> Vt[b][d][s] hi/lo
__global__ __launch_bounds__(256)
void transpose_pair(const bf16* __restrict__ Vh, const bf16* __restrict__ Vl,
                    bf16* __restrict__ Vth, bf16* __restrict__ Vtl)
{
    __shared__ bf16 th[32][33], tl[32][33];
    const int tx = threadIdx.x, ty = threadIdx.y;
    const int d0 = blockIdx.x * 32, s0 = blockIdx.y * 32;
    const size_t rowOff = (size_t)blockIdx.z * SS;
    #pragma unroll
    for (int j = 0; j < 32; j += 8) {
        const size_t src = (rowOff + s0 + ty + j) * ND + 2 * DD + d0 + tx;
        th[ty + j][tx] = Vh[src];
        tl[ty + j][tx] = Vl[src];
    }
    __syncthreads();
    const size_t bo = (size_t)blockIdx.z * DD * SS;
    #pragma unroll
    for (int j = 0; j < 32; j += 8) {
        const size_t addr = bo + (size_t)(d0 + ty + j) * SS + s0 + tx;
        Vth[addr] = th[tx][ty + j];
        Vtl[addr] = tl[tx][ty + j];
    }
}

__global__ __launch_bounds__(256)
void softmax_split_kernel(const float* __restrict__ Sm, bf16* __restrict__ Ph, bf16* __restrict__ Pl)
{
    __shared__ float red[256];
    const float* row = Sm + (size_t)blockIdx.x * SS;
    bf16* oh = Ph + (size_t)blockIdx.x * SS;
    bf16* ol = Pl + (size_t)blockIdx.x * SS;
    const int tid = threadIdx.x;

    float v[8];
    float m = -1e30f;
    #pragma unroll
    for (int i = 0; i < 8; ++i) { v[i] = row[tid + 256 * i]; m = fmaxf(m, v[i]); }
    red[tid] = m; __syncthreads();
    #pragma unroll
    for (int s = 128; s > 0; s >>= 1) { if (tid < s) red[tid] = fmaxf(red[tid], red[tid + s]); __syncthreads(); }
    m = red[0]; __syncthreads();

    float sum = 0.f;
    #pragma unroll
    for (int i = 0; i < 8; ++i) { v[i] = __expf(v[i] - m); sum += v[i]; }
    red[tid] = sum; __syncthreads();
    #pragma unroll
    for (int s = 128; s > 0; s >>= 1) { if (tid < s) red[tid] += red[tid + s]; __syncthreads(); }
    const float inv = __frcp_rn(red[0]);
    #pragma unroll
    for (int i = 0; i < 8; ++i) {
        const float p = v[i] * inv;
        const bf16 h = __float2bfloat16(p);
        oh[tid + 256 * i] = h;
        ol[tid + 256 * i] = __float2bfloat16(p - __bfloat162float(h));
    }
}

// ---------------- launch ----------------
extern "C" void kernel_launch(void* const* d_in, const int* in_sizes, int n_in,
                              void* d_out, int out_size)
{
    const float* x  = (const float*)d_in[0];
    const float* Wq = (const float*)d_in[1];
    const float* bq = (const float*)d_in[2];
    const float* Wk = (const float*)d_in[3];
    const float* bk = (const float*)d_in[4];
    const float* Wv = (const float*)d_in[5];
    const float* bv = (const float*)d_in[6];
    float* out = (float*)d_out;

    bf16 *xh, *xl, *Wth, *Wtl, *QKVh, *QKVl, *Vth, *Vtl, *Ph, *Pl;
    float *Sc, *bias;
    cudaGetSymbolAddress((void**)&xh, g_xh);     cudaGetSymbolAddress((void**)&xl, g_xl);
    cudaGetSymbolAddress((void**)&Wth, g_Wth);   cudaGetSymbolAddress((void**)&Wtl, g_Wtl);
    cudaGetSymbolAddress((void**)&QKVh, g_QKVh); cudaGetSymbolAddress((void**)&QKVl, g_QKVl);
    cudaGetSymbolAddress((void**)&Vth, g_Vth);   cudaGetSymbolAddress((void**)&Vtl, g_Vtl);
    cudaGetSymbolAddress((void**)&Sc, g_S);
    cudaGetSymbolAddress((void**)&Ph, g_Ph);     cudaGetSymbolAddress((void**)&Pl, g_Pl);
    cudaGetSymbolAddress((void**)&bias, g_bias);

    cudaFuncSetAttribute(tc_gemm<0, false>, cudaFuncAttributeMaxDynamicSharedMemorySize, SMEM_TOTAL);
    cudaFuncSetAttribute(tc_gemm<1, true>,  cudaFuncAttributeMaxDynamicSharedMemorySize, SMEM_TOTAL);

    const long long sQK = (long long)SS * ND;     // batch stride in QKV buffer
    const long long sS  = (long long)SS * SS;

    dim3 tg(DD / 32, DD / 32), tb(32, 8);

    // 0..4: prep (so that ncu -s 5 profiles the QKV GEMM)
    split_x_kernel<<<(BB * SS * DD / 4 + 255) / 256, 256>>>((const float4*)x, xh, xl, BB * SS * DD / 4);
    transpose_split_w<<<tg, tb>>>(Wq, Wth,                Wtl);
    transpose_split_w<<<tg, tb>>>(Wk, Wth + (size_t)DD * DD,     Wtl + (size_t)DD * DD);
    transpose_split_w<<<tg, tb>>>(Wv, Wth + (size_t)2 * DD * DD, Wtl + (size_t)2 * DD * DD);
    concat_bias<<<(ND + 255) / 256, 256>>>(bq, bk, bv, bias);

    // 5: merged QKV projection: [16384,3072] = x[16384,1024] * Wt^T  (+bias)
    dim3 g1(ND / 256, BB * SS / 128, 1);
    tc_gemm<1, true><<<g1, 256, SMEM_TOTAL>>>(xh, xl, Wth, Wtl, bias, nullptr, QKVh, QKVl,
                                              DD, DD, DD, 0, 0, 0, ND, 1.0f);

    // 6: V -> Vt [b][d][s]
    transpose_pair<<<dim3(DD / 32, SS / 32, BB), tb>>>(QKVh, QKVl, Vth, Vtl);

    // 7: scores = (Q K^T) / 32  (Q = cols 0-1023, K = cols 1024-2047 of QKV)
    dim3 g2(SS / 256, SS / 128, BB);
    tc_gemm<0, false><<<g2, 256, SMEM_TOTAL>>>(QKVh, QKVl, QKVh + DD, QKVl + DD, nullptr,
                                               Sc, nullptr, nullptr,
                                               DD, ND, ND, sQK, sQK, sS, SS, 0.03125f);

    // 8: softmax + split P
    softmax_split_kernel<<<BB * SS, 256>>>(Sc, Ph, Pl);

    // 9: out = P V   (A: P [q][s] ld 2048, B: Vt [d][s] ld 2048)
    dim3 g3(DD / 256, SS / 128, BB);
    tc_gemm<0, false><<<g3, 256, SMEM_TOTAL>>>(Ph, Pl, Vth, Vtl, nullptr, out, nullptr, nullptr,
                                               SS, SS, SS, sS, (long long)DD * SS, (long long)SS * DD,
                                               DD, 1.0f);
}

// round 6
// speedup vs baseline: 1.3874x; 1.3874x over previous
#include <cuda_runtime.h>
#include <cuda_fp16.h>
#include <cstdint>
#include <cstddef>

#define BB 8
#define SS 2048
#define DD 1024
#define ND 3072   // merged QKV output width

typedef __half fp16;

// ---------------- scratch ----------------
__device__ fp16 g_xh[(size_t)BB * SS * DD];
__device__ fp16 g_xl[(size_t)BB * SS * DD];
__device__ fp16 g_Wt[(size_t)ND * DD];           // [3072][1024] K-major, rounded fp16
__device__ float g_bias[ND];
__device__ fp16 g_QKVh[(size_t)BB * SS * ND];    // [16384][3072] hi
__device__ fp16 g_QKVl[(size_t)BB * SS * ND];    // lo (only Q part consumed)
__device__ fp16 g_Vt[(size_t)BB * DD * SS];      // [b][d][s] rounded fp16
__device__ float g_S[(size_t)BB * SS * SS];
__device__ fp16 g_Ph[(size_t)BB * SS * SS];
__device__ fp16 g_Pl[(size_t)BB * SS * SS];

// ---------------- PTX helpers ----------------
__device__ __forceinline__ uint32_t smem_u32(const void* p) {
    uint32_t a;
    asm("{ .reg .u64 t; cvta.to.shared.u64 t, %1; cvt.u32.u64 %0, t; }" : "=r"(a) : "l"(p));
    return a;
}
__device__ __forceinline__ void cp16(uint32_t s, const void* g) {
    asm volatile("cp.async.cg.shared.global [%0], [%1], 16;\n" :: "r"(s), "l"(g));
}
__device__ __forceinline__ void cp_commit() { asm volatile("cp.async.commit_group;\n" ::: "memory"); }
template <int N> __device__ __forceinline__ void cp_wait() {
    asm volatile("cp.async.wait_group %0;\n" :: "n"(N) : "memory");
}
__device__ __forceinline__ void ldsm_x4(uint32_t& r0, uint32_t& r1, uint32_t& r2, uint32_t& r3, uint32_t a) {
    asm volatile("ldmatrix.sync.aligned.m8n8.x4.shared.b16 {%0,%1,%2,%3}, [%4];"
                 : "=r"(r0), "=r"(r1), "=r"(r2), "=r"(r3) : "r"(a));
}
__device__ __forceinline__ void mma16816(float* d,
                                         uint32_t a0, uint32_t a1, uint32_t a2, uint32_t a3,
                                         uint32_t b0, uint32_t b1) {
    asm volatile("mma.sync.aligned.m16n8k16.row.col.f32.f16.f16.f32 "
                 "{%0,%1,%2,%3}, {%4,%5,%6,%7}, {%8,%9}, {%0,%1,%2,%3};"
                 : "+f"(d[0]), "+f"(d[1]), "+f"(d[2]), "+f"(d[3])
                 : "r"(a0), "r"(a1), "r"(a2), "r"(a3), "r"(b0), "r"(b1));
}

#define SW128(o) ((o) ^ (((o) >> 3) & 0x70))

// smem stage: A hi (16K) + A lo (16K) + B single (32K) = 64K; 3 stages = 192K
static constexpr int S_AH = 0, S_AL = 16384, S_B = 32768;
static constexpr int STAGE = 65536;
static constexpr int STAGES = 3;
static constexpr int SMEM_TOTAL = STAGES * STAGE;   // 196608

// ---------------- 2-pass fp16 mma.sync GEMM ----------------
// C[M,N] = (Ah+Al)[M,K] x B[N,K]^T, fp32 accum.  CTA 128x256, 512 thr, warp 32x64.
// EPI: 0 = fp32 out, 1 = fp16 hi/lo split out
template <int EPI, bool HASB>
__global__ __launch_bounds__(512, 1)
void tc_gemm(const fp16* __restrict__ Ah_, const fp16* __restrict__ Al_,
             const fp16* __restrict__ B_,
             const float* __restrict__ bias,
             float* __restrict__ Co, fp16* __restrict__ Coh, fp16* __restrict__ Col,
             int Kd, int lda, int ldb,
             long long sA, long long sB, long long sC, int ldo, float scale)
{
    extern __shared__ char smem[];
    const uint32_t su = smem_u32(smem);
    const int tid = threadIdx.x, lane = tid & 31, wid = tid >> 5;
    const int wm = wid >> 2, wn = wid & 3;           // 4(m) x 4(n), warp tile 32x64
    const int rowBase = blockIdx.y * 128, colBase = blockIdx.x * 256;

    Ah_ += (long long)blockIdx.z * sA;  Al_ += (long long)blockIdx.z * sA;
    B_  += (long long)blockIdx.z * sB;
    if (EPI == 0) Co += (long long)blockIdx.z * sC;
    else { Coh += (long long)blockIdx.z * sC; Col += (long long)blockIdx.z * sC; }

    float acc[16][4] = {};                            // [im*8+in][4]

    const int NC = Kd >> 6;

    auto load_stage = [&](int s, int k0) {
        const uint32_t base = su + s * STAGE;
        #pragma unroll
        for (int j = 0; j < 2; ++j) {                 // A: 128 rows, hi+lo
            const int idx = tid + j * 512, r = idx >> 3, cu = idx & 7;
            const size_t go = (size_t)(rowBase + r) * lda + k0 + cu * 8;
            const uint32_t so = SW128((uint32_t)(r * 128 + cu * 16));
            cp16(base + S_AH + so, Ah_ + go);
            cp16(base + S_AL + so, Al_ + go);
        }
        #pragma unroll
        for (int j = 0; j < 4; ++j) {                 // B: 256 rows, single
            const int idx = tid + j * 512, r = idx >> 3, cu = idx & 7;
            const size_t go = (size_t)(colBase + r) * ldb + k0 + cu * 8;
            const uint32_t so = SW128((uint32_t)(r * 128 + cu * 16));
            cp16(base + S_B + so, B_ + go);
        }
        cp_commit();
    };

    load_stage(0, 0);
    load_stage(1, 64);

    const uint32_t sw   = (lane & 7) << 4;
    const uint32_t arow = (lane & 7) + (lane & 8);
    const uint32_t koff = (lane & 16);

    for (int c = 0; c < NC; ++c) {
        if (c + 2 < NC) load_stage((c + 2) % STAGES, (c + 2) << 6);
        else            cp_commit();
        cp_wait<2>();
        __syncthreads();

        const uint32_t base = su + (c % STAGES) * STAGE;
        #pragma unroll
        for (int ks = 0; ks < 4; ++ks) {
            uint32_t ah[2][4], al[2][4];
            #pragma unroll
            for (int im = 0; im < 2; ++im) {
                const uint32_t off = (wm * 32 + im * 16 + arow) * 128 + ks * 32 + koff;
                ldsm_x4(ah[im][0], ah[im][1], ah[im][2], ah[im][3], (base + S_AH + off) ^ sw);
                ldsm_x4(al[im][0], al[im][1], al[im][2], al[im][3], (base + S_AL + off) ^ sw);
            }
            uint32_t bh[4][4];
            #pragma unroll
            for (int ip = 0; ip < 4; ++ip) {
                const uint32_t off = (wn * 64 + ip * 16 + arow) * 128 + ks * 32 + koff;
                ldsm_x4(bh[ip][0], bh[ip][1], bh[ip][2], bh[ip][3], (base + S_B + off) ^ sw);
            }
            #pragma unroll
            for (int im = 0; im < 2; ++im)
                #pragma unroll
                for (int in = 0; in < 8; ++in) {
                    float* d = acc[im * 8 + in];
                    const int ip = in >> 1, sb = in & 1;
                    mma16816(d, ah[im][0], ah[im][1], ah[im][2], ah[im][3],
                             bh[ip][sb], bh[ip][2 + sb]);                      // hi pass
                    mma16816(d, al[im][0], al[im][1], al[im][2], al[im][3],
                             bh[ip][sb], bh[ip][2 + sb]);                      // lo pass
                }
        }
        __syncthreads();
    }

    // ---------------- epilogue ----------------
    #pragma unroll
    for (int im = 0; im < 2; ++im) {
        #pragma unroll
        for (int in = 0; in < 8; ++in) {
            const float* d = acc[im * 8 + in];
            const int row0 = rowBase + wm * 32 + im * 16 + (lane >> 2);
            const int col0 = colBase + wn * 64 + in * 8 + 2 * (lane & 3);
            #pragma unroll
            for (int h = 0; h < 2; ++h) {
                const int row = row0 + h * 8;
                float v0 = d[2 * h + 0], v1 = d[2 * h + 1];
                if (HASB) { v0 += bias[col0]; v1 += bias[col0 + 1]; }
                v0 *= scale; v1 *= scale;
                if (EPI == 0) {
                    float2 f2; f2.x = v0; f2.y = v1;
                    *reinterpret_cast<float2*>(Co + (size_t)row * ldo + col0) = f2;
                } else {
                    const fp16 h0 = __float2half(v0), h1 = __float2half(v1);
                    __half2 H; H.x = h0; H.y = h1;
                    __half2 L;
                    L.x = __float2half(v0 - __half2float(h0));
                    L.y = __float2half(v1 - __half2float(h1));
                    *reinterpret_cast<__half2*>(Coh + (size_t)row * ldo + col0) = H;
                    *reinterpret_cast<__half2*>(Col + (size_t)row * ldo + col0) = L;
                }
            }
        }
    }
}

// ---------------- aux kernels ----------------
__global__ __launch_bounds__(256)
void split_x_kernel(const float4* __restrict__ src, fp16* __restrict__ hi, fp16* __restrict__ lo, int n4)
{
    const int i = blockIdx.x * 256 + threadIdx.x;
    if (i >= n4) return;
    const float4 v = src[i];
    fp16 h0 = __float2half(v.x), h1 = __float2half(v.y);
    fp16 h2 = __float2half(v.z), h3 = __float2half(v.w);
    __half2 H0; H0.x = h0; H0.y = h1;
    __half2 H1; H1.x = h2; H1.y = h3;
    __half2 L0, L1;
    L0.x = __float2half(v.x - __half2float(h0));
    L0.y = __float2half(v.y - __half2float(h1));
    L1.x = __float2half(v.z - __half2float(h2));
    L1.y = __float2half(v.w - __half2float(h3));
    reinterpret_cast<__half2*>(hi)[2 * i] = H0;
    reinterpret_cast<__half2*>(hi)[2 * i + 1] = H1;
    reinterpret_cast<__half2*>(lo)[2 * i] = L0;
    reinterpret_cast<__half2*>(lo)[2 * i + 1] = L1;
}

// W [1024][1024] fp32 -> Wt section [n][k] fp16 rounded (dst pre-offset)
__global__ __launch_bounds__(256)
void transpose_round_w(const float* __restrict__ W, fp16* __restrict__ T)
{
    __shared__ float t[32][33];
    const int tx = threadIdx.x, ty = threadIdx.y;
    const int x0 = blockIdx.x * 32, y0 = blockIdx.y * 32;
    #pragma unroll
    for (int j = 0; j < 32; j += 8)
        t[ty + j][tx] = W[(size_t)(y0 + ty + j) * DD + x0 + tx];
    __syncthreads();
    #pragma unroll
    for (int j = 0; j < 32; j += 8)
        T[(size_t)(x0 + ty + j) * DD + y0 + tx] = __float2half(t[tx][ty + j]);
}

__global__ void concat_bias(const float* bq, const float* bk, const float* bv, float* o)
{
    const int i = blockIdx.x * 256 + threadIdx.x;
    if (i < DD) o[i] = bq[i];
    else if (i < 2 * DD) o[i] = bk[i - DD];
    else if (i < ND) o[i] = bv[i - 2 * DD];
}

// V slice of QKVh (cols 2048..3071) [b*2048+s][3072] -> Vt[b][d][s]
__global__ __launch_bounds__(256)
void transpose_v(const fp16* __restrict__ Vh, fp16* __restrict__ Vt)
{
    __shared__ fp16 t[32][33];
    const int tx = threadIdx.x, ty = threadIdx.y;
    const int d0 = blockIdx.x * 32, s0 = blockIdx.y * 32;
    const size_t rowOff = (size_t)blockIdx.z * SS;
    #pragma unroll
    for (int j = 0; j < 32; j += 8)
        t[ty + j][tx] = Vh[(rowOff + s0 + ty + j) * ND + 2 * DD + d0 + tx];
    __syncthreads();
    const size_t bo = (size_t)blockIdx.z * DD * SS;
    #pragma unroll
    for (int j = 0; j < 32; j += 8)
        Vt[bo + (size_t)(d0 + ty + j) * SS + s0 + tx] = t[tx][ty + j];
}

__global__ __launch_bounds__(256)
void softmax_split_kernel(const float* __restrict__ Sm, fp16* __restrict__ Ph, fp16* __restrict__ Pl)
{
    __shared__ float red[256];
    const float* row = Sm + (size_t)blockIdx.x * SS;
    fp16* oh = Ph + (size_t)blockIdx.x * SS;
    fp16* ol = Pl + (size_t)blockIdx.x * SS;
    const int tid = threadIdx.x;

    float v[8];
    float m = -1e30f;
    #pragma unroll
    for (int i = 0; i < 8; ++i) { v[i] = row[tid + 256 * i]; m = fmaxf(m, v[i]); }
    red[tid] = m; __syncthreads();
    #pragma unroll
    for (int s = 128; s > 0; s >>= 1) { if (tid < s) red[tid] = fmaxf(red[tid], red[tid + s]); __syncthreads(); }
    m = red[0]; __syncthreads();

    float sum = 0.f;
    #pragma unroll
    for (int i = 0; i < 8; ++i) { v[i] = __expf(v[i] - m); sum += v[i]; }
    red[tid] = sum; __syncthreads();
    #pragma unroll
    for (int s = 128; s > 0; s >>= 1) { if (tid < s) red[tid] += red[tid + s]; __syncthreads(); }
    const float inv = __frcp_rn(red[0]);
    #pragma unroll
    for (int i = 0; i < 8; ++i) {
        const float p = v[i] * inv;
        const fp16 h = __float2half(p);
        oh[tid + 256 * i] = h;
        ol[tid + 256 * i] = __float2half(p - __half2float(h));
    }
}

// ---------------- launch ----------------
extern "C" void kernel_launch(void* const* d_in, const int* in_sizes, int n_in,
                              void* d_out, int out_size)
{
    const float* x  = (const float*)d_in[0];
    const float* Wq = (const float*)d_in[1];
    const float* bq = (const float*)d_in[2];
    const float* Wk = (const float*)d_in[3];
    const float* bk = (const float*)d_in[4];
    const float* Wv = (const float*)d_in[5];
    const float* bv = (const float*)d_in[6];
    float* out = (float*)d_out;

    fp16 *xh, *xl, *Wt, *QKVh, *QKVl, *Vt, *Ph, *Pl;
    float *Sc, *bias;
    cudaGetSymbolAddress((void**)&xh, g_xh);     cudaGetSymbolAddress((void**)&xl, g_xl);
    cudaGetSymbolAddress((void**)&Wt, g_Wt);
    cudaGetSymbolAddress((void**)&QKVh, g_QKVh); cudaGetSymbolAddress((void**)&QKVl, g_QKVl);
    cudaGetSymbolAddress((void**)&Vt, g_Vt);
    cudaGetSymbolAddress((void**)&Sc, g_S);
    cudaGetSymbolAddress((void**)&Ph, g_Ph);     cudaGetSymbolAddress((void**)&Pl, g_Pl);
    cudaGetSymbolAddress((void**)&bias, g_bias);

    cudaFuncSetAttribute(tc_gemm<0, false>, cudaFuncAttributeMaxDynamicSharedMemorySize, SMEM_TOTAL);
    cudaFuncSetAttribute(tc_gemm<1, true>,  cudaFuncAttributeMaxDynamicSharedMemorySize, SMEM_TOTAL);

    const long long sQK = (long long)SS * ND;
    const long long sS  = (long long)SS * SS;

    dim3 tg(DD / 32, DD / 32), tb(32, 8);

    // launches 0..4: prep (ncu -s 5 then lands on the QKV GEMM)
    split_x_kernel<<<(BB * SS * DD / 4 + 255) / 256, 256>>>((const float4*)x, xh, xl, BB * SS * DD / 4);
    transpose_round_w<<<tg, tb>>>(Wq, Wt);
    transpose_round_w<<<tg, tb>>>(Wk, Wt + (size_t)DD * DD);
    transpose_round_w<<<tg, tb>>>(Wv, Wt + (size_t)2 * DD * DD);
    concat_bias<<<(ND + 255) / 256, 256>>>(bq, bk, bv, bias);

    // 5: merged QKV projection [16384,3072]
    dim3 g1(ND / 256, BB * SS / 128, 1);
    tc_gemm<1, true><<<g1, 512, SMEM_TOTAL>>>(xh, xl, Wt, bias, nullptr, QKVh, QKVl,
                                              DD, DD, DD, 0, 0, 0, ND, 1.0f);

    // 6: V -> Vt [b][d][s]
    transpose_v<<<dim3(DD / 32, SS / 32, BB), tb>>>(QKVh, Vt);

    // 7: scores = (Q K^T)/32 ; A = Q split, B = K hi (rounded)
    dim3 g2(SS / 256, SS / 128, BB);
    tc_gemm<0, false><<<g2, 512, SMEM_TOTAL>>>(QKVh, QKVl, QKVh + DD, nullptr,
                                               Sc, nullptr, nullptr,
                                               DD, ND, ND, sQK, sQK, sS, SS, 0.03125f);

    // 8: softmax + split P
    softmax_split_kernel<<<BB * SS, 256>>>(Sc, Ph, Pl);

    // 9: out = P V ; A = P split, B = Vt (rounded)
    dim3 g3(DD / 256, SS / 128, BB);
    tc_gemm<0, false><<<g3, 512, SMEM_TOTAL>>>(Ph, Pl, Vt, nullptr, out, nullptr, nullptr,
                                               SS, SS, SS, sS, (long long)DD * SS, (long long)SS * DD,
                                               DD, 1.0f);
}

// round 7
// speedup vs baseline: 1.8919x; 1.3636x over previous
#include <cuda_runtime.h>
#include <cuda_fp16.h>
#include <cstdint>
#include <cstddef>

#define BB 8
#define SS 2048
#define DD 1024
#define ND 3072   // merged QKV output width

typedef __half fp16;

// ---------------- scratch ----------------
__device__ fp16 g_xh[(size_t)BB * SS * DD];
__device__ fp16 g_xl[(size_t)BB * SS * DD];
__device__ fp16 g_Wt[(size_t)ND * DD];           // [3072][1024] K-major, rounded fp16
__device__ float g_bias[ND];
__device__ fp16 g_QKVh[(size_t)BB * SS * ND];    // [16384][3072]
__device__ fp16 g_Vt[(size_t)BB * DD * SS];      // [b][d][s]
__device__ float g_S[(size_t)BB * SS * SS];
__device__ fp16 g_Ph[(size_t)BB * SS * SS];

// ---------------- PTX helpers ----------------
__device__ __forceinline__ uint32_t smem_u32(const void* p) {
    uint32_t a;
    asm("{ .reg .u64 t; cvta.to.shared.u64 t, %1; cvt.u32.u64 %0, t; }" : "=r"(a) : "l"(p));
    return a;
}
__device__ __forceinline__ void cp16(uint32_t s, const void* g) {
    asm volatile("cp.async.cg.shared.global [%0], [%1], 16;\n" :: "r"(s), "l"(g));
}
__device__ __forceinline__ void cp_commit() { asm volatile("cp.async.commit_group;\n" ::: "memory"); }
template <int N> __device__ __forceinline__ void cp_wait() {
    asm volatile("cp.async.wait_group %0;\n" :: "n"(N) : "memory");
}
__device__ __forceinline__ void ldsm_x4(uint32_t& r0, uint32_t& r1, uint32_t& r2, uint32_t& r3, uint32_t a) {
    asm volatile("ldmatrix.sync.aligned.m8n8.x4.shared.b16 {%0,%1,%2,%3}, [%4];"
                 : "=r"(r0), "=r"(r1), "=r"(r2), "=r"(r3) : "r"(a));
}
__device__ __forceinline__ void mma16816(float* d,
                                         uint32_t a0, uint32_t a1, uint32_t a2, uint32_t a3,
                                         uint32_t b0, uint32_t b1) {
    asm volatile("mma.sync.aligned.m16n8k16.row.col.f32.f16.f16.f32 "
                 "{%0,%1,%2,%3}, {%4,%5,%6,%7}, {%8,%9}, {%0,%1,%2,%3};"
                 : "+f"(d[0]), "+f"(d[1]), "+f"(d[2]), "+f"(d[3])
                 : "r"(a0), "r"(a1), "r"(a2), "r"(a3), "r"(b0), "r"(b1));
}

#define SW128(o) ((o) ^ (((o) >> 3) & 0x70))

// smem stage: A hi (16K) + A lo (16K, unused when !SPLITA) + B (32K) = 64K; 3 stages
static constexpr int S_AH = 0, S_AL = 16384, S_B = 32768;
static constexpr int STAGE = 65536;
static constexpr int STAGES = 3;
static constexpr int SMEM_TOTAL = STAGES * STAGE;   // 196608

// ---------------- fp16 mma.sync GEMM, CTA 128x256, 512 thr, warp 32x64 ----------------
// SPLITA: C = (Ah+Al) x B^T (2-pass).  !SPLITA: C = Ah x B^T (1-pass).
// EPI: 0 = fp32 out, 1 = fp16 (rounded) out
template <bool SPLITA, int EPI, bool HASB>
__global__ __launch_bounds__(512, 1)
void tc_gemm(const fp16* __restrict__ Ah_, const fp16* __restrict__ Al_,
             const fp16* __restrict__ B_,
             const float* __restrict__ bias,
             float* __restrict__ Co, fp16* __restrict__ Coh,
             int Kd, int lda, int ldb,
             long long sA, long long sB, long long sC, int ldo, float scale)
{
    extern __shared__ char smem[];
    const uint32_t su = smem_u32(smem);
    const int tid = threadIdx.x, lane = tid & 31, wid = tid >> 5;
    const int wm = wid >> 2, wn = wid & 3;           // 4(m) x 4(n), warp tile 32x64
    const int rowBase = blockIdx.y * 128, colBase = blockIdx.x * 256;

    Ah_ += (long long)blockIdx.z * sA;
    if (SPLITA) Al_ += (long long)blockIdx.z * sA;
    B_  += (long long)blockIdx.z * sB;
    if (EPI == 0) Co += (long long)blockIdx.z * sC;
    else          Coh += (long long)blockIdx.z * sC;

    float acc[16][4] = {};                            // [im*8+in][4]

    const int NC = Kd >> 6;

    auto load_stage = [&](int s, int k0) {
        const uint32_t base = su + s * STAGE;
        #pragma unroll
        for (int j = 0; j < 2; ++j) {                 // A: 128 rows
            const int idx = tid + j * 512, r = idx >> 3, cu = idx & 7;
            const size_t go = (size_t)(rowBase + r) * lda + k0 + cu * 8;
            const uint32_t so = SW128((uint32_t)(r * 128 + cu * 16));
            cp16(base + S_AH + so, Ah_ + go);
            if (SPLITA) cp16(base + S_AL + so, Al_ + go);
        }
        #pragma unroll
        for (int j = 0; j < 4; ++j) {                 // B: 256 rows
            const int idx = tid + j * 512, r = idx >> 3, cu = idx & 7;
            const size_t go = (size_t)(colBase + r) * ldb + k0 + cu * 8;
            const uint32_t so = SW128((uint32_t)(r * 128 + cu * 16));
            cp16(base + S_B + so, B_ + go);
        }
        cp_commit();
    };

    load_stage(0, 0);
    load_stage(1, 64);

    const uint32_t sw   = (lane & 7) << 4;
    const uint32_t arow = (lane & 7) + (lane & 8);
    const uint32_t koff = (lane & 16);

    for (int c = 0; c < NC; ++c) {
        if (c + 2 < NC) load_stage((c + 2) % STAGES, (c + 2) << 6);
        else            cp_commit();
        cp_wait<2>();
        __syncthreads();

        const uint32_t base = su + (c % STAGES) * STAGE;
        #pragma unroll
        for (int ks = 0; ks < 4; ++ks) {
            uint32_t ah[2][4], al[2][4];
            #pragma unroll
            for (int im = 0; im < 2; ++im) {
                const uint32_t off = (wm * 32 + im * 16 + arow) * 128 + ks * 32 + koff;
                ldsm_x4(ah[im][0], ah[im][1], ah[im][2], ah[im][3], (base + S_AH + off) ^ sw);
                if (SPLITA)
                    ldsm_x4(al[im][0], al[im][1], al[im][2], al[im][3], (base + S_AL + off) ^ sw);
            }
            uint32_t bh[4][4];
            #pragma unroll
            for (int ip = 0; ip < 4; ++ip) {
                const uint32_t off = (wn * 64 + ip * 16 + arow) * 128 + ks * 32 + koff;
                ldsm_x4(bh[ip][0], bh[ip][1], bh[ip][2], bh[ip][3], (base + S_B + off) ^ sw);
            }
            #pragma unroll
            for (int im = 0; im < 2; ++im)
                #pragma unroll
                for (int in = 0; in < 8; ++in) {
                    float* d = acc[im * 8 + in];
                    const int ip = in >> 1, sb = in & 1;
                    mma16816(d, ah[im][0], ah[im][1], ah[im][2], ah[im][3],
                             bh[ip][sb], bh[ip][2 + sb]);                      // hi pass
                    if (SPLITA)
                        mma16816(d, al[im][0], al[im][1], al[im][2], al[im][3],
                                 bh[ip][sb], bh[ip][2 + sb]);                  // lo pass
                }
        }
        __syncthreads();
    }

    // ---------------- epilogue ----------------
    #pragma unroll
    for (int im = 0; im < 2; ++im) {
        #pragma unroll
        for (int in = 0; in < 8; ++in) {
            const float* d = acc[im * 8 + in];
            const int row0 = rowBase + wm * 32 + im * 16 + (lane >> 2);
            const int col0 = colBase + wn * 64 + in * 8 + 2 * (lane & 3);
            #pragma unroll
            for (int h = 0; h < 2; ++h) {
                const int row = row0 + h * 8;
                float v0 = d[2 * h + 0], v1 = d[2 * h + 1];
                if (HASB) { v0 += bias[col0]; v1 += bias[col0 + 1]; }
                v0 *= scale; v1 *= scale;
                if (EPI == 0) {
                    float2 f2; f2.x = v0; f2.y = v1;
                    *reinterpret_cast<float2*>(Co + (size_t)row * ldo + col0) = f2;
                } else {
                    __half2 H; H.x = __float2half(v0); H.y = __float2half(v1);
                    *reinterpret_cast<__half2*>(Coh + (size_t)row * ldo + col0) = H;
                }
            }
        }
    }
}

// ---------------- aux kernels ----------------
__global__ __launch_bounds__(256)
void split_x_kernel(const float4* __restrict__ src, fp16* __restrict__ hi, fp16* __restrict__ lo, int n4)
{
    const int i = blockIdx.x * 256 + threadIdx.x;
    if (i >= n4) return;
    const float4 v = src[i];
    fp16 h0 = __float2half(v.x), h1 = __float2half(v.y);
    fp16 h2 = __float2half(v.z), h3 = __float2half(v.w);
    __half2 H0; H0.x = h0; H0.y = h1;
    __half2 H1; H1.x = h2; H1.y = h3;
    __half2 L0, L1;
    L0.x = __float2half(v.x - __half2float(h0));
    L0.y = __float2half(v.y - __half2float(h1));
    L1.x = __float2half(v.z - __half2float(h2));
    L1.y = __float2half(v.w - __half2float(h3));
    reinterpret_cast<__half2*>(hi)[2 * i] = H0;
    reinterpret_cast<__half2*>(hi)[2 * i + 1] = H1;
    reinterpret_cast<__half2*>(lo)[2 * i] = L0;
    reinterpret_cast<__half2*>(lo)[2 * i + 1] = L1;
}

// W [1024][1024] fp32 -> Wt section [n][k] fp16 rounded (dst pre-offset)
__global__ __launch_bounds__(256)
void transpose_round_w(const float* __restrict__ W, fp16* __restrict__ T)
{
    __shared__ float t[32][33];
    const int tx = threadIdx.x, ty = threadIdx.y;
    const int x0 = blockIdx.x * 32, y0 = blockIdx.y * 32;
    #pragma unroll
    for (int j = 0; j < 32; j += 8)
        t[ty + j][tx] = W[(size_t)(y0 + ty + j) * DD + x0 + tx];
    __syncthreads();
    #pragma unroll
    for (int j = 0; j < 32; j += 8)
        T[(size_t)(x0 + ty + j) * DD + y0 + tx] = __float2half(t[tx][ty + j]);
}

__global__ void concat_bias(const float* bq, const float* bk, const float* bv, float* o)
{
    const int i = blockIdx.x * 256 + threadIdx.x;
    if (i < DD) o[i] = bq[i];
    else if (i < 2 * DD) o[i] = bk[i - DD];
    else if (i < ND) o[i] = bv[i - 2 * DD];
}

// V slice of QKVh (cols 2048..3071) [b*2048+s][3072] -> Vt[b][d][s]
__global__ __launch_bounds__(256)
void transpose_v(const fp16* __restrict__ Vh, fp16* __restrict__ Vt)
{
    __shared__ fp16 t[32][33];
    const int tx = threadIdx.x, ty = threadIdx.y;
    const int d0 = blockIdx.x * 32, s0 = blockIdx.y * 32;
    const size_t rowOff = (size_t)blockIdx.z * SS;
    #pragma unroll
    for (int j = 0; j < 32; j += 8)
        t[ty + j][tx] = Vh[(rowOff + s0 + ty + j) * ND + 2 * DD + d0 + tx];
    __syncthreads();
    const size_t bo = (size_t)blockIdx.z * DD * SS;
    #pragma unroll
    for (int j = 0; j < 32; j += 8)
        Vt[bo + (size_t)(d0 + ty + j) * SS + s0 + tx] = t[tx][ty + j];
}

__global__ __launch_bounds__(256)
void softmax_round_kernel(const float* __restrict__ Sm, fp16* __restrict__ Ph)
{
    __shared__ float red[256];
    const float* row = Sm + (size_t)blockIdx.x * SS;
    fp16* oh = Ph + (size_t)blockIdx.x * SS;
    const int tid = threadIdx.x;

    float v[8];
    float m = -1e30f;
    #pragma unroll
    for (int i = 0; i < 8; ++i) { v[i] = row[tid + 256 * i]; m = fmaxf(m, v[i]); }
    red[tid] = m; __syncthreads();
    #pragma unroll
    for (int s = 128; s > 0; s >>= 1) { if (tid < s) red[tid] = fmaxf(red[tid], red[tid + s]); __syncthreads(); }
    m = red[0]; __syncthreads();

    float sum = 0.f;
    #pragma unroll
    for (int i = 0; i < 8; ++i) { v[i] = __expf(v[i] - m); sum += v[i]; }
    red[tid] = sum; __syncthreads();
    #pragma unroll
    for (int s = 128; s > 0; s >>= 1) { if (tid < s) red[tid] += red[tid + s]; __syncthreads(); }
    const float inv = __frcp_rn(red[0]);
    #pragma unroll
    for (int i = 0; i < 8; i += 2) {
        __half2 H;
        H.x = __float2half(v[i] * inv);
        H.y = __float2half(v[i + 1] * inv);
        // elements i, i+1 are 256 apart, not adjacent — store individually
        oh[tid + 256 * i]       = H.x;
        oh[tid + 256 * (i + 1)] = H.y;
    }
}

// ---------------- launch ----------------
extern "C" void kernel_launch(void* const* d_in, const int* in_sizes, int n_in,
                              void* d_out, int out_size)
{
    const float* x  = (const float*)d_in[0];
    const float* Wq = (const float*)d_in[1];
    const float* bq = (const float*)d_in[2];
    const float* Wk = (const float*)d_in[3];
    const float* bk = (const float*)d_in[4];
    const float* Wv = (const float*)d_in[5];
    const float* bv = (const float*)d_in[6];
    float* out = (float*)d_out;

    fp16 *xh, *xl, *Wt, *QKVh, *Vt, *Ph;
    float *Sc, *bias;
    cudaGetSymbolAddress((void**)&xh, g_xh);     cudaGetSymbolAddress((void**)&xl, g_xl);
    cudaGetSymbolAddress((void**)&Wt, g_Wt);
    cudaGetSymbolAddress((void**)&QKVh, g_QKVh);
    cudaGetSymbolAddress((void**)&Vt, g_Vt);
    cudaGetSymbolAddress((void**)&Sc, g_S);
    cudaGetSymbolAddress((void**)&Ph, g_Ph);
    cudaGetSymbolAddress((void**)&bias, g_bias);

    cudaFuncSetAttribute(tc_gemm<true, 1, true>,   cudaFuncAttributeMaxDynamicSharedMemorySize, SMEM_TOTAL);
    cudaFuncSetAttribute(tc_gemm<false, 0, false>, cudaFuncAttributeMaxDynamicSharedMemorySize, SMEM_TOTAL);

    const long long sQK = (long long)SS * ND;
    const long long sS  = (long long)SS * SS;

    dim3 tg(DD / 32, DD / 32), tb(32, 8);

    // prep
    split_x_kernel<<<(BB * SS * DD / 4 + 255) / 256, 256>>>((const float4*)x, xh, xl, BB * SS * DD / 4);
    transpose_round_w<<<tg, tb>>>(Wq, Wt);
    transpose_round_w<<<tg, tb>>>(Wk, Wt + (size_t)DD * DD);
    transpose_round_w<<<tg, tb>>>(Wv, Wt + (size_t)2 * DD * DD);
    concat_bias<<<(ND + 255) / 256, 256>>>(bq, bk, bv, bias);

    // merged QKV projection [16384,3072], 2-pass (x split), fp16-rounded output
    dim3 g1(ND / 256, BB * SS / 128, 1);
    tc_gemm<true, 1, true><<<g1, 512, SMEM_TOTAL>>>(xh, xl, Wt, bias, nullptr, QKVh,
                                                    DD, DD, DD, 0, 0, 0, ND, 1.0f);

    // V -> Vt [b][d][s]
    transpose_v<<<dim3(DD / 32, SS / 32, BB), tb>>>(QKVh, Vt);

    // scores = (Q K^T)/32, 1-pass
    dim3 g2(SS / 256, SS / 128, BB);
    tc_gemm<false, 0, false><<<g2, 512, SMEM_TOTAL>>>(QKVh, nullptr, QKVh + DD, nullptr,
                                                      Sc, nullptr,
                                                      DD, ND, ND, sQK, sQK, sS, SS, 0.03125f);

    // softmax (fp32 in, fp16 out)
    softmax_round_kernel<<<BB * SS, 256>>>(Sc, Ph);

    // out = P V, 1-pass
    dim3 g3(DD / 256, SS / 128, BB);
    tc_gemm<false, 0, false><<<g3, 512, SMEM_TOTAL>>>(Ph, nullptr, Vt, nullptr,
                                                      out, nullptr,
                                                      SS, SS, SS, sS, (long long)DD * SS,
                                                      (long long)SS * DD, DD, 1.0f);
}

// round 8
// speedup vs baseline: 2.4680x; 1.3045x over previous
#include <cuda_runtime.h>
#include <cuda_fp16.h>
#include <cstdint>
#include <cstddef>

#define BB 8
#define SS 2048
#define DD 1024
#define ND 3072   // merged QKV output width

typedef __half fp16;

// ---------------- scratch ----------------
__device__ fp16 g_xh[(size_t)BB * SS * DD];      // x rounded to fp16
__device__ fp16 g_Wt[(size_t)ND * DD];           // [3072][1024] K-major, rounded fp16
__device__ float g_bias[ND];
__device__ fp16 g_QKVh[(size_t)BB * SS * ND];    // [16384][3072]
__device__ fp16 g_Vt[(size_t)BB * DD * SS];      // [b][d][s]
__device__ float g_S[(size_t)BB * SS * SS];
__device__ fp16 g_Ph[(size_t)BB * SS * SS];

// ---------------- PTX helpers ----------------
__device__ __forceinline__ uint32_t smem_u32(const void* p) {
    uint32_t a;
    asm("{ .reg .u64 t; cvta.to.shared.u64 t, %1; cvt.u32.u64 %0, t; }" : "=r"(a) : "l"(p));
    return a;
}
__device__ __forceinline__ void cp16(uint32_t s, const void* g) {
    asm volatile("cp.async.cg.shared.global [%0], [%1], 16;\n" :: "r"(s), "l"(g));
}
__device__ __forceinline__ void cp_commit() { asm volatile("cp.async.commit_group;\n" ::: "memory"); }
template <int N> __device__ __forceinline__ void cp_wait() {
    asm volatile("cp.async.wait_group %0;\n" :: "n"(N) : "memory");
}
__device__ __forceinline__ void ldsm_x4(uint32_t& r0, uint32_t& r1, uint32_t& r2, uint32_t& r3, uint32_t a) {
    asm volatile("ldmatrix.sync.aligned.m8n8.x4.shared.b16 {%0,%1,%2,%3}, [%4];"
                 : "=r"(r0), "=r"(r1), "=r"(r2), "=r"(r3) : "r"(a));
}
__device__ __forceinline__ void mma16816(float* d,
                                         uint32_t a0, uint32_t a1, uint32_t a2, uint32_t a3,
                                         uint32_t b0, uint32_t b1) {
    asm volatile("mma.sync.aligned.m16n8k16.row.col.f32.f16.f16.f32 "
                 "{%0,%1,%2,%3}, {%4,%5,%6,%7}, {%8,%9}, {%0,%1,%2,%3};"
                 : "+f"(d[0]), "+f"(d[1]), "+f"(d[2]), "+f"(d[3])
                 : "r"(a0), "r"(a1), "r"(a2), "r"(a3), "r"(b0), "r"(b1));
}

#define SW128(o) ((o) ^ (((o) >> 3) & 0x70))

// smem stage: A (16K) + B (32K) = 48K; 3 stages = 144K
static constexpr int S_A = 0, S_B = 16384;
static constexpr int STAGE = 49152;
static constexpr int STAGES = 3;
static constexpr int SMEM_TOTAL = STAGES * STAGE;   // 147456

// ---------------- 1-pass fp16 mma.sync GEMM, CTA 128x256, 512 thr, warp 32x64 ----------------
// C[M,N] = A[M,K] x B[N,K]^T, fp32 accum. EPI: 0 = fp32 out, 1 = fp16 out
template <int EPI, bool HASB>
__global__ __launch_bounds__(512, 1)
void tc_gemm(const fp16* __restrict__ A_, const fp16* __restrict__ B_,
             const float* __restrict__ bias,
             float* __restrict__ Co, fp16* __restrict__ Coh,
             int Kd, int lda, int ldb,
             long long sA, long long sB, long long sC, int ldo, float scale)
{
    extern __shared__ char smem[];
    const uint32_t su = smem_u32(smem);
    const int tid = threadIdx.x, lane = tid & 31, wid = tid >> 5;
    const int wm = wid >> 2, wn = wid & 3;           // 4(m) x 4(n), warp tile 32x64
    const int rowBase = blockIdx.y * 128, colBase = blockIdx.x * 256;

    A_ += (long long)blockIdx.z * sA;
    B_ += (long long)blockIdx.z * sB;
    if (EPI == 0) Co += (long long)blockIdx.z * sC;
    else          Coh += (long long)blockIdx.z * sC;

    float acc[16][4] = {};                            // [im*8+in][4]

    const int NC = Kd >> 6;

    auto load_stage = [&](int s, int k0) {
        const uint32_t base = su + s * STAGE;
        #pragma unroll
        for (int j = 0; j < 2; ++j) {                 // A: 128 rows
            const int idx = tid + j * 512, r = idx >> 3, cu = idx & 7;
            const size_t go = (size_t)(rowBase + r) * lda + k0 + cu * 8;
            const uint32_t so = SW128((uint32_t)(r * 128 + cu * 16));
            cp16(base + S_A + so, A_ + go);
        }
        #pragma unroll
        for (int j = 0; j < 4; ++j) {                 // B: 256 rows
            const int idx = tid + j * 512, r = idx >> 3, cu = idx & 7;
            const size_t go = (size_t)(colBase + r) * ldb + k0 + cu * 8;
            const uint32_t so = SW128((uint32_t)(r * 128 + cu * 16));
            cp16(base + S_B + so, B_ + go);
        }
        cp_commit();
    };

    load_stage(0, 0);
    load_stage(1, 64);

    const uint32_t sw   = (lane & 7) << 4;
    const uint32_t arow = (lane & 7) + (lane & 8);
    const uint32_t koff = (lane & 16);

    for (int c = 0; c < NC; ++c) {
        if (c + 2 < NC) load_stage((c + 2) % STAGES, (c + 2) << 6);
        else            cp_commit();
        cp_wait<2>();
        __syncthreads();

        const uint32_t base = su + (c % STAGES) * STAGE;
        #pragma unroll
        for (int ks = 0; ks < 4; ++ks) {
            uint32_t ah[2][4];
            #pragma unroll
            for (int im = 0; im < 2; ++im) {
                const uint32_t off = (wm * 32 + im * 16 + arow) * 128 + ks * 32 + koff;
                ldsm_x4(ah[im][0], ah[im][1], ah[im][2], ah[im][3], (base + S_A + off) ^ sw);
            }
            uint32_t bh[4][4];
            #pragma unroll
            for (int ip = 0; ip < 4; ++ip) {
                const uint32_t off = (wn * 64 + ip * 16 + arow) * 128 + ks * 32 + koff;
                ldsm_x4(bh[ip][0], bh[ip][1], bh[ip][2], bh[ip][3], (base + S_B + off) ^ sw);
            }
            #pragma unroll
            for (int im = 0; im < 2; ++im)
                #pragma unroll
                for (int in = 0; in < 8; ++in) {
                    float* d = acc[im * 8 + in];
                    const int ip = in >> 1, sb = in & 1;
                    mma16816(d, ah[im][0], ah[im][1], ah[im][2], ah[im][3],
                             bh[ip][sb], bh[ip][2 + sb]);
                }
        }
        __syncthreads();
    }

    // ---------------- epilogue ----------------
    #pragma unroll
    for (int im = 0; im < 2; ++im) {
        #pragma unroll
        for (int in = 0; in < 8; ++in) {
            const float* d = acc[im * 8 + in];
            const int row0 = rowBase + wm * 32 + im * 16 + (lane >> 2);
            const int col0 = colBase + wn * 64 + in * 8 + 2 * (lane & 3);
            #pragma unroll
            for (int h = 0; h < 2; ++h) {
                const int row = row0 + h * 8;
                float v0 = d[2 * h + 0], v1 = d[2 * h + 1];
                if (HASB) { v0 += bias[col0]; v1 += bias[col0 + 1]; }
                v0 *= scale; v1 *= scale;
                if (EPI == 0) {
                    float2 f2; f2.x = v0; f2.y = v1;
                    *reinterpret_cast<float2*>(Co + (size_t)row * ldo + col0) = f2;
                } else {
                    __half2 H; H.x = __float2half(v0); H.y = __float2half(v1);
                    *reinterpret_cast<__half2*>(Coh + (size_t)row * ldo + col0) = H;
                }
            }
        }
    }
}

// ---------------- aux kernels ----------------
__global__ __launch_bounds__(256)
void round_x_kernel(const float4* __restrict__ src, fp16* __restrict__ hi, int n4)
{
    const int i = blockIdx.x * 256 + threadIdx.x;
    if (i >= n4) return;
    const float4 v = src[i];
    __half2 H0; H0.x = __float2half(v.x); H0.y = __float2half(v.y);
    __half2 H1; H1.x = __float2half(v.z); H1.y = __float2half(v.w);
    reinterpret_cast<__half2*>(hi)[2 * i] = H0;
    reinterpret_cast<__half2*>(hi)[2 * i + 1] = H1;
}

// W [1024][1024] fp32 -> Wt section [n][k] fp16 rounded (dst pre-offset)
__global__ __launch_bounds__(256)
void transpose_round_w(const float* __restrict__ W, fp16* __restrict__ T)
{
    __shared__ float t[32][33];
    const int tx = threadIdx.x, ty = threadIdx.y;
    const int x0 = blockIdx.x * 32, y0 = blockIdx.y * 32;
    #pragma unroll
    for (int j = 0; j < 32; j += 8)
        t[ty + j][tx] = W[(size_t)(y0 + ty + j) * DD + x0 + tx];
    __syncthreads();
    #pragma unroll
    for (int j = 0; j < 32; j += 8)
        T[(size_t)(x0 + ty + j) * DD + y0 + tx] = __float2half(t[tx][ty + j]);
}

__global__ void concat_bias(const float* bq, const float* bk, const float* bv, float* o)
{
    const int i = blockIdx.x * 256 + threadIdx.x;
    if (i < DD) o[i] = bq[i];
    else if (i < 2 * DD) o[i] = bk[i - DD];
    else if (i < ND) o[i] = bv[i - 2 * DD];
}

// V slice of QKVh (cols 2048..3071) -> Vt[b][d][s]
__global__ __launch_bounds__(256)
void transpose_v(const fp16* __restrict__ Vh, fp16* __restrict__ Vt)
{
    __shared__ fp16 t[32][33];
    const int tx = threadIdx.x, ty = threadIdx.y;
    const int d0 = blockIdx.x * 32, s0 = blockIdx.y * 32;
    const size_t rowOff = (size_t)blockIdx.z * SS;
    #pragma unroll
    for (int j = 0; j < 32; j += 8)
        t[ty + j][tx] = Vh[(rowOff + s0 + ty + j) * ND + 2 * DD + d0 + tx];
    __syncthreads();
    const size_t bo = (size_t)blockIdx.z * DD * SS;
    #pragma unroll
    for (int j = 0; j < 32; j += 8)
        Vt[bo + (size_t)(d0 + ty + j) * SS + s0 + tx] = t[tx][ty + j];
}

__global__ __launch_bounds__(256)
void softmax_round_kernel(const float* __restrict__ Sm, fp16* __restrict__ Ph)
{
    __shared__ float red[256];
    const float* row = Sm + (size_t)blockIdx.x * SS;
    fp16* oh = Ph + (size_t)blockIdx.x * SS;
    const int tid = threadIdx.x;

    float v[8];
    float m = -1e30f;
    #pragma unroll
    for (int i = 0; i < 8; ++i) { v[i] = row[tid + 256 * i]; m = fmaxf(m, v[i]); }
    red[tid] = m; __syncthreads();
    #pragma unroll
    for (int s = 128; s > 0; s >>= 1) { if (tid < s) red[tid] = fmaxf(red[tid], red[tid + s]); __syncthreads(); }
    m = red[0]; __syncthreads();

    float sum = 0.f;
    #pragma unroll
    for (int i = 0; i < 8; ++i) { v[i] = __expf(v[i] - m); sum += v[i]; }
    red[tid] = sum; __syncthreads();
    #pragma unroll
    for (int s = 128; s > 0; s >>= 1) { if (tid < s) red[tid] += red[tid + s]; __syncthreads(); }
    const float inv = __frcp_rn(red[0]);
    #pragma unroll
    for (int i = 0; i < 8; ++i)
        oh[tid + 256 * i] = __float2half(v[i] * inv);
}

// ---------------- launch ----------------
extern "C" void kernel_launch(void* const* d_in, const int* in_sizes, int n_in,
                              void* d_out, int out_size)
{
    const float* x  = (const float*)d_in[0];
    const float* Wq = (const float*)d_in[1];
    const float* bq = (const float*)d_in[2];
    const float* Wk = (const float*)d_in[3];
    const float* bk = (const float*)d_in[4];
    const float* Wv = (const float*)d_in[5];
    const float* bv = (const float*)d_in[6];
    float* out = (float*)d_out;

    fp16 *xh, *Wt, *QKVh, *Vt, *Ph;
    float *Sc, *bias;
    cudaGetSymbolAddress((void**)&xh, g_xh);
    cudaGetSymbolAddress((void**)&Wt, g_Wt);
    cudaGetSymbolAddress((void**)&QKVh, g_QKVh);
    cudaGetSymbolAddress((void**)&Vt, g_Vt);
    cudaGetSymbolAddress((void**)&Sc, g_S);
    cudaGetSymbolAddress((void**)&Ph, g_Ph);
    cudaGetSymbolAddress((void**)&bias, g_bias);

    cudaFuncSetAttribute(tc_gemm<1, true>,  cudaFuncAttributeMaxDynamicSharedMemorySize, SMEM_TOTAL);
    cudaFuncSetAttribute(tc_gemm<0, false>, cudaFuncAttributeMaxDynamicSharedMemorySize, SMEM_TOTAL);

    const long long sQK = (long long)SS * ND;
    const long long sS  = (long long)SS * SS;

    dim3 tg(DD / 32, DD / 32), tb(32, 8);

    // prep
    round_x_kernel<<<(BB * SS * DD / 4 + 255) / 256, 256>>>((const float4*)x, xh, BB * SS * DD / 4);
    transpose_round_w<<<tg, tb>>>(Wq, Wt);
    transpose_round_w<<<tg, tb>>>(Wk, Wt + (size_t)DD * DD);
    transpose_round_w<<<tg, tb>>>(Wv, Wt + (size_t)2 * DD * DD);
    concat_bias<<<(ND + 255) / 256, 256>>>(bq, bk, bv, bias);

    // merged QKV projection [16384,3072], 1-pass, fp16 out
    dim3 g1(ND / 256, BB * SS / 128, 1);
    tc_gemm<1, true><<<g1, 512, SMEM_TOTAL>>>(xh, Wt, bias, nullptr, QKVh,
                                              DD, DD, DD, 0, 0, 0, ND, 1.0f);

    // V -> Vt [b][d][s]
    transpose_v<<<dim3(DD / 32, SS / 32, BB), tb>>>(QKVh, Vt);

    // scores = (Q K^T)/32, 1-pass, fp32 out
    dim3 g2(SS / 256, SS / 128, BB);
    tc_gemm<0, false><<<g2, 512, SMEM_TOTAL>>>(QKVh, QKVh + DD, nullptr,
                                               Sc, nullptr,
                                               DD, ND, ND, sQK, sQK, sS, SS, 0.03125f);

    // softmax (fp32 in, fp16 out)
    softmax_round_kernel<<<BB * SS, 256>>>(Sc, Ph);

    // out = P V, 1-pass, fp32 out
    dim3 g3(DD / 256, SS / 128, BB);
    tc_gemm<0, false><<<g3, 512, SMEM_TOTAL>>>(Ph, Vt, nullptr,
                                               out, nullptr,
                                               SS, SS, SS, sS, (long long)DD * SS,
                                               (long long)SS * DD, DD, 1.0f);
}

// round 11
// speedup vs baseline: 2.5165x; 1.0197x over previous
#include <cuda_runtime.h>
#include <cuda_fp16.h>
#include <cstdint>
#include <cstddef>

#define BB 8
#define SS 2048
#define DD 1024
#define ND 3072   // merged QKV output width

typedef __half fp16;

// ---------------- scratch ----------------
__device__ fp16 g_xh[(size_t)BB * SS * DD];      // x rounded to fp16
__device__ fp16 g_Wt[(size_t)ND * DD];           // [3072][1024] K-major, rounded fp16
__device__ float g_bias[ND];
__device__ fp16 g_QKVh[(size_t)BB * SS * ND];    // [16384][3072]
__device__ fp16 g_Vt[(size_t)BB * DD * SS];      // [b][d][s]
__device__ fp16 g_Pu[(size_t)BB * SS * SS];      // unnormalized exp(scores), fp16
__device__ float g_rsinv[(size_t)BB * SS];       // 1 / rowsum(exp(scores))

// ---------------- PTX helpers ----------------
__device__ __forceinline__ uint32_t smem_u32(const void* p) {
    uint32_t a;
    asm("{ .reg .u64 t; cvta.to.shared.u64 t, %1; cvt.u32.u64 %0, t; }" : "=r"(a) : "l"(p));
    return a;
}
__device__ __forceinline__ void cp16(uint32_t s, const void* g) {
    asm volatile("cp.async.cg.shared.global [%0], [%1], 16;\n" :: "r"(s), "l"(g));
}
__device__ __forceinline__ void cp_commit() { asm volatile("cp.async.commit_group;\n" ::: "memory"); }
template <int N> __device__ __forceinline__ void cp_wait() {
    asm volatile("cp.async.wait_group %0;\n" :: "n"(N) : "memory");
}
__device__ __forceinline__ void ldsm_x4(uint32_t& r0, uint32_t& r1, uint32_t& r2, uint32_t& r3, uint32_t a) {
    asm volatile("ldmatrix.sync.aligned.m8n8.x4.shared.b16 {%0,%1,%2,%3}, [%4];"
                 : "=r"(r0), "=r"(r1), "=r"(r2), "=r"(r3) : "r"(a));
}
__device__ __forceinline__ void mma16816(float* d,
                                         uint32_t a0, uint32_t a1, uint32_t a2, uint32_t a3,
                                         uint32_t b0, uint32_t b1) {
    asm volatile("mma.sync.aligned.m16n8k16.row.col.f32.f16.f16.f32 "
                 "{%0,%1,%2,%3}, {%4,%5,%6,%7}, {%8,%9}, {%0,%1,%2,%3};"
                 : "+f"(d[0]), "+f"(d[1]), "+f"(d[2]), "+f"(d[3])
                 : "r"(a0), "r"(a1), "r"(a2), "r"(a3), "r"(b0), "r"(b1));
}

#define SW128(o) ((o) ^ (((o) >> 3) & 0x70))

// smem stage: A (16K) + B (32K) = 48K; 3 stages = 144K
static constexpr int S_A = 0, S_B = 16384;
static constexpr int STAGE = 49152;
static constexpr int STAGES = 3;
static constexpr int SMEM_TOTAL = STAGES * STAGE;   // 147456

// ---------------- 1-pass fp16 mma.sync GEMM, CTA 128x256, 512 thr, warp 32x64 ----------------
// C[M,N] = A[M,K] x B[N,K]^T, fp32 accum.
// EPI: 1 = fp16 out (+bias)        [QKV projection]
//      2 = fp16 exp(scale*acc) out [scores -> unnormalized P]
//      3 = fp32 out * rsinv[row]   [PV with deferred softmax normalization]
template <int EPI, bool HASB>
__global__ __launch_bounds__(512, 1)
void tc_gemm(const fp16* __restrict__ A_, const fp16* __restrict__ B_,
             const float* __restrict__ bias, const float* __restrict__ rs,
             float* __restrict__ Co, fp16* __restrict__ Coh,
             int Kd, int lda, int ldb,
             long long sA, long long sB, long long sC, int ldo, float scale)
{
    extern __shared__ char smem[];
    const uint32_t su = smem_u32(smem);
    const int tid = threadIdx.x, lane = tid & 31, wid = tid >> 5;
    const int wm = wid >> 2, wn = wid & 3;           // 4(m) x 4(n), warp tile 32x64
    const int rowBase = blockIdx.y * 128, colBase = blockIdx.x * 256;

    A_ += (long long)blockIdx.z * sA;
    B_ += (long long)blockIdx.z * sB;
    if (EPI == 3) { Co += (long long)blockIdx.z * sC; rs += (long long)blockIdx.z * SS; }
    else          Coh += (long long)blockIdx.z * sC;

    float acc[16][4] = {};                            // [im*8+in][4]

    const int NC = Kd >> 6;

    auto load_stage = [&](int s, int k0) {
        const uint32_t base = su + s * STAGE;
        #pragma unroll
        for (int j = 0; j < 2; ++j) {                 // A: 128 rows
            const int idx = tid + j * 512, r = idx >> 3, cu = idx & 7;
            const size_t go = (size_t)(rowBase + r) * lda + k0 + cu * 8;
            const uint32_t so = SW128((uint32_t)(r * 128 + cu * 16));
            cp16(base + S_A + so, A_ + go);
        }
        #pragma unroll
        for (int j = 0; j < 4; ++j) {                 // B: 256 rows
            const int idx = tid + j * 512, r = idx >> 3, cu = idx & 7;
            const size_t go = (size_t)(colBase + r) * ldb + k0 + cu * 8;
            const uint32_t so = SW128((uint32_t)(r * 128 + cu * 16));
            cp16(base + S_B + so, B_ + go);
        }
        cp_commit();
    };

    load_stage(0, 0);
    load_stage(1, 64);

    const uint32_t sw   = (lane & 7) << 4;
    const uint32_t arow = (lane & 7) + (lane & 8);
    const uint32_t koff = (lane & 16);

    for (int c = 0; c < NC; ++c) {
        if (c + 2 < NC) load_stage((c + 2) % STAGES, (c + 2) << 6);
        else            cp_commit();
        cp_wait<2>();
        __syncthreads();

        const uint32_t base = su + (c % STAGES) * STAGE;
        #pragma unroll
        for (int ks = 0; ks < 4; ++ks) {
            uint32_t ah[2][4];
            #pragma unroll
            for (int im = 0; im < 2; ++im) {
                const uint32_t off = (wm * 32 + im * 16 + arow) * 128 + ks * 32 + koff;
                ldsm_x4(ah[im][0], ah[im][1], ah[im][2], ah[im][3], (base + S_A + off) ^ sw);
            }
            uint32_t bh[4][4];
            #pragma unroll
            for (int ip = 0; ip < 4; ++ip) {
                const uint32_t off = (wn * 64 + ip * 16 + arow) * 128 + ks * 32 + koff;
                ldsm_x4(bh[ip][0], bh[ip][1], bh[ip][2], bh[ip][3], (base + S_B + off) ^ sw);
            }
            #pragma unroll
            for (int im = 0; im < 2; ++im)
                #pragma unroll
                for (int in = 0; in < 8; ++in) {
                    float* d = acc[im * 8 + in];
                    const int ip = in >> 1, sb = in & 1;
                    mma16816(d, ah[im][0], ah[im][1], ah[im][2], ah[im][3],
                             bh[ip][sb], bh[ip][2 + sb]);
                }
        }
        __syncthreads();
    }

    // ---------------- epilogue ----------------
    #pragma unroll
    for (int im = 0; im < 2; ++im) {
        #pragma unroll
        for (int in = 0; in < 8; ++in) {
            const float* d = acc[im * 8 + in];
            const int row0 = rowBase + wm * 32 + im * 16 + (lane >> 2);
            const int col0 = colBase + wn * 64 + in * 8 + 2 * (lane & 3);
            #pragma unroll
            for (int h = 0; h < 2; ++h) {
                const int row = row0 + h * 8;
                float v0 = d[2 * h + 0], v1 = d[2 * h + 1];
                if (HASB) { v0 += bias[col0]; v1 += bias[col0 + 1]; }
                v0 *= scale; v1 *= scale;
                if (EPI == 1) {
                    __half2 H; H.x = __float2half(v0); H.y = __float2half(v1);
                    *reinterpret_cast<__half2*>(Coh + (size_t)row * ldo + col0) = H;
                } else if (EPI == 2) {
                    __half2 H;
                    H.x = __float2half(__expf(v0));
                    H.y = __float2half(__expf(v1));
                    *reinterpret_cast<__half2*>(Coh + (size_t)row * ldo + col0) = H;
                } else {
                    const float r = rs[row - rowBase + rowBase];   // rs indexed by local row in batch
                    float2 f2; f2.x = v0 * r; f2.y = v1 * r;
                    *reinterpret_cast<float2*>(Co + (size_t)row * ldo + col0) = f2;
                }
            }
        }
    }
}

// ---------------- aux kernels ----------------
__global__ __launch_bounds__(256)
void round_x_kernel(const float4* __restrict__ src, fp16* __restrict__ hi, int n4)
{
    const int i = blockIdx.x * 256 + threadIdx.x;
    if (i >= n4) return;
    const float4 v = src[i];
    __half2 H0; H0.x = __float2half(v.x); H0.y = __float2half(v.y);
    __half2 H1; H1.x = __float2half(v.z); H1.y = __float2half(v.w);
    reinterpret_cast<__half2*>(hi)[2 * i] = H0;
    reinterpret_cast<__half2*>(hi)[2 * i + 1] = H1;
}

// W [1024][1024] fp32 -> Wt section [n][k] fp16 rounded (dst pre-offset)
__global__ __launch_bounds__(256)
void transpose_round_w(const float* __restrict__ W, fp16* __restrict__ T)
{
    __shared__ float t[32][33];
    const int tx = threadIdx.x, ty = threadIdx.y;
    const int x0 = blockIdx.x * 32, y0 = blockIdx.y * 32;
    #pragma unroll
    for (int j = 0; j < 32; j += 8)
        t[ty + j][tx] = W[(size_t)(y0 + ty + j) * DD + x0 + tx];
    __syncthreads();
    #pragma unroll
    for (int j = 0; j < 32; j += 8)
        T[(size_t)(x0 + ty + j) * DD + y0 + tx] = __float2half(t[tx][ty + j]);
}

__global__ void concat_bias(const float* bq, const float* bk, const float* bv, float* o)
{
    const int i = blockIdx.x * 256 + threadIdx.x;
    if (i < DD) o[i] = bq[i];
    else if (i < 2 * DD) o[i] = bk[i - DD];
    else if (i < ND) o[i] = bv[i - 2 * DD];
}

// V slice of QKVh (cols 2048..3071) -> Vt[b][d][s]
__global__ __launch_bounds__(256)
void transpose_v(const fp16* __restrict__ Vh, fp16* __restrict__ Vt)
{
    __shared__ fp16 t[32][33];
    const int tx = threadIdx.x, ty = threadIdx.y;
    const int d0 = blockIdx.x * 32, s0 = blockIdx.y * 32;
    const size_t rowOff = (size_t)blockIdx.z * SS;
    #pragma unroll
    for (int j = 0; j < 32; j += 8)
        t[ty + j][tx] = Vh[(rowOff + s0 + ty + j) * ND + 2 * DD + d0 + tx];
    __syncthreads();
    const size_t bo = (size_t)blockIdx.z * DD * SS;
    #pragma unroll
    for (int j = 0; j < 32; j += 8)
        Vt[bo + (size_t)(d0 + ty + j) * SS + s0 + tx] = t[tx][ty + j];
}

// 1 / rowsum of unnormalized P (fp16 in, fp32 out); one block per row
__global__ __launch_bounds__(256)
void rowsum_inv_kernel(const fp16* __restrict__ Pu, float* __restrict__ rsinv)
{
    __shared__ float red[256];
    const __half2* row = reinterpret_cast<const __half2*>(Pu + (size_t)blockIdx.x * SS);
    const int tid = threadIdx.x;
    float sum = 0.f;
    #pragma unroll
    for (int i = 0; i < 4; ++i) {
        const float2 p = __half22float2(row[tid + 256 * i]);
        sum += p.x + p.y;
    }
    red[tid] = sum; __syncthreads();
    #pragma unroll
    for (int s = 128; s > 0; s >>= 1) { if (tid < s) red[tid] += red[tid + s]; __syncthreads(); }
    if (tid == 0) rsinv[blockIdx.x] = __frcp_rn(red[0]);
}

// ---------------- launch ----------------
extern "C" void kernel_launch(void* const* d_in, const int* in_sizes, int n_in,
                              void* d_out, int out_size)
{
    const float* x  = (const float*)d_in[0];
    const float* Wq = (const float*)d_in[1];
    const float* bq = (const float*)d_in[2];
    const float* Wk = (const float*)d_in[3];
    const float* bk = (const float*)d_in[4];
    const float* Wv = (const float*)d_in[5];
    const float* bv = (const float*)d_in[6];
    float* out = (float*)d_out;

    fp16 *xh, *Wt, *QKVh, *Vt, *Pu;
    float *bias, *rsinv;
    cudaGetSymbolAddress((void**)&xh, g_xh);
    cudaGetSymbolAddress((void**)&Wt, g_Wt);
    cudaGetSymbolAddress((void**)&QKVh, g_QKVh);
    cudaGetSymbolAddress((void**)&Vt, g_Vt);
    cudaGetSymbolAddress((void**)&Pu, g_Pu);
    cudaGetSymbolAddress((void**)&bias, g_bias);
    cudaGetSymbolAddress((void**)&rsinv, g_rsinv);

    cudaFuncSetAttribute(tc_gemm<1, true>,  cudaFuncAttributeMaxDynamicSharedMemorySize, SMEM_TOTAL);
    cudaFuncSetAttribute(tc_gemm<2, false>, cudaFuncAttributeMaxDynamicSharedMemorySize, SMEM_TOTAL);
    cudaFuncSetAttribute(tc_gemm<3, false>, cudaFuncAttributeMaxDynamicSharedMemorySize, SMEM_TOTAL);

    const long long sQK = (long long)SS * ND;
    const long long sS  = (long long)SS * SS;

    dim3 tg(DD / 32, DD / 32), tb(32, 8);

    // prep
    round_x_kernel<<<(BB * SS * DD / 4 + 255) / 256, 256>>>((const float4*)x, xh, BB * SS * DD / 4);
    transpose_round_w<<<tg, tb>>>(Wq, Wt);
    transpose_round_w<<<tg, tb>>>(Wk, Wt + (size_t)DD * DD);
    transpose_round_w<<<tg, tb>>>(Wv, Wt + (size_t)2 * DD * DD);
    concat_bias<<<(ND + 255) / 256, 256>>>(bq, bk, bv, bias);

    // merged QKV projection [16384,3072], fp16 out
    dim3 g1(ND / 256, BB * SS / 128, 1);
    tc_gemm<1, true><<<g1, 512, SMEM_TOTAL>>>(xh, Wt, bias, nullptr, nullptr, QKVh,
                                              DD, DD, DD, 0, 0, 0, ND, 1.0f);

    // V -> Vt [b][d][s]
    transpose_v<<<dim3(DD / 32, SS / 32, BB), tb>>>(QKVh, Vt);

    // Pu = exp((Q K^T)/32), fp16 out — fused softmax numerator
    dim3 g2(SS / 256, SS / 128, BB);
    tc_gemm<2, false><<<g2, 512, SMEM_TOTAL>>>(QKVh, QKVh + DD, nullptr, nullptr,
                                               nullptr, Pu,
                                               DD, ND, ND, sQK, sQK, sS, SS, 0.03125f);

    // rsinv = 1 / rowsum(Pu)
    rowsum_inv_kernel<<<BB * SS, 256>>>(Pu, rsinv);

    // out = (Pu V) * rsinv
    dim3 g3(DD / 256, SS / 128, BB);
    tc_gemm<3, false><<<g3, 512, SMEM_TOTAL>>>(Pu, Vt, nullptr, rsinv,
                                               out, nullptr,
                                               SS, SS, SS, sS, (long long)DD * SS,
                                               (long long)SS * DD, DD, 1.0f);
}

// round 12
// speedup vs baseline: 2.7960x; 1.1111x over previous
#include <cuda_runtime.h>
#include <cuda_fp16.h>
#include <cstdint>
#include <cstddef>

#define BB 8
#define SS 2048
#define DD 1024
#define ND 3072   // merged QKV output width

typedef __half fp16;

// ---------------- scratch ----------------
__device__ fp16 g_xh[(size_t)BB * SS * DD];      // x rounded to fp16
__device__ fp16 g_Wt[(size_t)ND * DD];           // [3072][1024] K-major, rounded fp16
__device__ float g_bias[ND];
__device__ fp16 g_QKVh[(size_t)BB * SS * ND];    // [16384][3072]
__device__ fp16 g_Vt[(size_t)BB * DD * SS];      // [b][d][s]
__device__ fp16 g_Pu[(size_t)BB * SS * SS];      // unnormalized exp(scores), fp16
__device__ float g_rsinv[(size_t)BB * SS];       // 1 / rowsum(exp(scores))

// ---------------- PTX helpers ----------------
__device__ __forceinline__ uint32_t smem_u32(const void* p) {
    uint32_t a;
    asm("{ .reg .u64 t; cvta.to.shared.u64 t, %1; cvt.u32.u64 %0, t; }" : "=r"(a) : "l"(p));
    return a;
}
__device__ __forceinline__ void cp16(uint32_t s, const void* g) {
    asm volatile("cp.async.cg.shared.global [%0], [%1], 16;\n" :: "r"(s), "l"(g));
}
__device__ __forceinline__ void cp_commit() { asm volatile("cp.async.commit_group;\n" ::: "memory"); }
template <int N> __device__ __forceinline__ void cp_wait() {
    asm volatile("cp.async.wait_group %0;\n" :: "n"(N) : "memory");
}
__device__ __forceinline__ void ldsm_x4(uint32_t& r0, uint32_t& r1, uint32_t& r2, uint32_t& r3, uint32_t a) {
    asm volatile("ldmatrix.sync.aligned.m8n8.x4.shared.b16 {%0,%1,%2,%3}, [%4];"
                 : "=r"(r0), "=r"(r1), "=r"(r2), "=r"(r3) : "r"(a));
}
__device__ __forceinline__ void mma16816(float* d,
                                         uint32_t a0, uint32_t a1, uint32_t a2, uint32_t a3,
                                         uint32_t b0, uint32_t b1) {
    asm volatile("mma.sync.aligned.m16n8k16.row.col.f32.f16.f16.f32 "
                 "{%0,%1,%2,%3}, {%4,%5,%6,%7}, {%8,%9}, {%0,%1,%2,%3};"
                 : "+f"(d[0]), "+f"(d[1]), "+f"(d[2]), "+f"(d[3])
                 : "r"(a0), "r"(a1), "r"(a2), "r"(a3), "r"(b0), "r"(b1));
}

#define SW128(o) ((o) ^ (((o) >> 3) & 0x70))

// smem stage: A (16K) + B (16K) = 32K; 3 stages = 96K; 2 CTAs/SM = 192K
static constexpr int S_A = 0, S_B = 16384;
static constexpr int STAGE = 32768;
static constexpr int STAGES = 3;
static constexpr int SMEM_TOTAL = STAGES * STAGE;   // 98304

// ---------------- 1-pass fp16 mma.sync GEMM, CTA 128x128, 256 thr, warp 64x32 ----------------
// C[M,N] = A[M,K] x B[N,K]^T, fp32 accum.
// EPI: 1 = fp16 out (+bias)        [QKV projection]
//      2 = fp16 exp(scale*acc) out [scores -> unnormalized P]
//      3 = fp32 out * rsinv[row]   [PV with deferred softmax normalization]
template <int EPI, bool HASB>
__global__ __launch_bounds__(256, 2)
void tc_gemm(const fp16* __restrict__ A_, const fp16* __restrict__ B_,
             const float* __restrict__ bias, const float* __restrict__ rs,
             float* __restrict__ Co, fp16* __restrict__ Coh,
             int Kd, int lda, int ldb,
             long long sA, long long sB, long long sC, int ldo, float scale)
{
    extern __shared__ char smem[];
    const uint32_t su = smem_u32(smem);
    const int tid = threadIdx.x, lane = tid & 31, wid = tid >> 5;
    const int wm = wid >> 2, wn = wid & 3;           // 2(m) x 4(n), warp tile 64x32
    const int rowBase = blockIdx.y * 128, colBase = blockIdx.x * 128;

    A_ += (long long)blockIdx.z * sA;
    B_ += (long long)blockIdx.z * sB;
    if (EPI == 3) { Co += (long long)blockIdx.z * sC; rs += (long long)blockIdx.z * SS; }
    else          Coh += (long long)blockIdx.z * sC;

    float acc[16][4] = {};                            // [im*4+in][4]

    const int NC = Kd >> 6;

    auto load_stage = [&](int s, int k0) {
        const uint32_t base = su + s * STAGE;
        #pragma unroll
        for (int j = 0; j < 4; ++j) {                 // A: 128 rows x 64 fp16
            const int idx = tid + j * 256, r = idx >> 3, cu = idx & 7;
            const size_t go = (size_t)(rowBase + r) * lda + k0 + cu * 8;
            const uint32_t so = SW128((uint32_t)(r * 128 + cu * 16));
            cp16(base + S_A + so, A_ + go);
        }
        #pragma unroll
        for (int j = 0; j < 4; ++j) {                 // B: 128 rows x 64 fp16
            const int idx = tid + j * 256, r = idx >> 3, cu = idx & 7;
            const size_t go = (size_t)(colBase + r) * ldb + k0 + cu * 8;
            const uint32_t so = SW128((uint32_t)(r * 128 + cu * 16));
            cp16(base + S_B + so, B_ + go);
        }
        cp_commit();
    };

    load_stage(0, 0);
    load_stage(1, 64);

    const uint32_t sw   = (lane & 7) << 4;
    const uint32_t arow = (lane & 7) + (lane & 8);
    const uint32_t koff = (lane & 16);

    for (int c = 0; c < NC; ++c) {
        if (c + 2 < NC) load_stage((c + 2) % STAGES, (c + 2) << 6);
        else            cp_commit();
        cp_wait<2>();
        __syncthreads();

        const uint32_t base = su + (c % STAGES) * STAGE;
        #pragma unroll
        for (int ks = 0; ks < 4; ++ks) {
            uint32_t ah[4][4];
            #pragma unroll
            for (int im = 0; im < 4; ++im) {
                const uint32_t off = (wm * 64 + im * 16 + arow) * 128 + ks * 32 + koff;
                ldsm_x4(ah[im][0], ah[im][1], ah[im][2], ah[im][3], (base + S_A + off) ^ sw);
            }
            uint32_t bh[2][4];
            #pragma unroll
            for (int ip = 0; ip < 2; ++ip) {
                const uint32_t off = (wn * 32 + ip * 16 + arow) * 128 + ks * 32 + koff;
                ldsm_x4(bh[ip][0], bh[ip][1], bh[ip][2], bh[ip][3], (base + S_B + off) ^ sw);
            }
            #pragma unroll
            for (int im = 0; im < 4; ++im)
                #pragma unroll
                for (int in = 0; in < 4; ++in) {
                    float* d = acc[im * 4 + in];
                    const int ip = in >> 1, sb = in & 1;
                    mma16816(d, ah[im][0], ah[im][1], ah[im][2], ah[im][3],
                             bh[ip][sb], bh[ip][2 + sb]);
                }
        }
        __syncthreads();
    }

    // ---------------- epilogue ----------------
    #pragma unroll
    for (int im = 0; im < 4; ++im) {
        #pragma unroll
        for (int in = 0; in < 4; ++in) {
            const float* d = acc[im * 4 + in];
            const int row0 = rowBase + wm * 64 + im * 16 + (lane >> 2);
            const int col0 = colBase + wn * 32 + in * 8 + 2 * (lane & 3);
            #pragma unroll
            for (int h = 0; h < 2; ++h) {
                const int row = row0 + h * 8;
                float v0 = d[2 * h + 0], v1 = d[2 * h + 1];
                if (HASB) { v0 += bias[col0]; v1 += bias[col0 + 1]; }
                v0 *= scale; v1 *= scale;
                if (EPI == 1) {
                    __half2 H; H.x = __float2half(v0); H.y = __float2half(v1);
                    *reinterpret_cast<__half2*>(Coh + (size_t)row * ldo + col0) = H;
                } else if (EPI == 2) {
                    __half2 H;
                    H.x = __float2half(__expf(v0));
                    H.y = __float2half(__expf(v1));
                    *reinterpret_cast<__half2*>(Coh + (size_t)row * ldo + col0) = H;
                } else {
                    const float r = rs[row];
                    float2 f2; f2.x = v0 * r; f2.y = v1 * r;
                    *reinterpret_cast<float2*>(Co + (size_t)row * ldo + col0) = f2;
                }
            }
        }
    }
}

// ---------------- aux kernels ----------------
__global__ __launch_bounds__(256)
void round_x_kernel(const float4* __restrict__ src, fp16* __restrict__ hi, int n4)
{
    const int i = blockIdx.x * 256 + threadIdx.x;
    if (i >= n4) return;
    const float4 v = src[i];
    __half2 H0; H0.x = __float2half(v.x); H0.y = __float2half(v.y);
    __half2 H1; H1.x = __float2half(v.z); H1.y = __float2half(v.w);
    reinterpret_cast<__half2*>(hi)[2 * i] = H0;
    reinterpret_cast<__half2*>(hi)[2 * i + 1] = H1;
}

// all three W [1024][1024] fp32 -> Wt sections [n][k] fp16 (z selects the matrix)
__global__ __launch_bounds__(256)
void transpose_round_w_all(const float* __restrict__ Wq, const float* __restrict__ Wk,
                           const float* __restrict__ Wv, fp16* __restrict__ T)
{
    __shared__ float t[32][33];
    const float* W = (blockIdx.z == 0) ? Wq : (blockIdx.z == 1) ? Wk : Wv;
    fp16* Td = T + (size_t)blockIdx.z * DD * DD;
    const int tx = threadIdx.x, ty = threadIdx.y;
    const int x0 = blockIdx.x * 32, y0 = blockIdx.y * 32;
    #pragma unroll
    for (int j = 0; j < 32; j += 8)
        t[ty + j][tx] = W[(size_t)(y0 + ty + j) * DD + x0 + tx];
    __syncthreads();
    #pragma unroll
    for (int j = 0; j < 32; j += 8)
        Td[(size_t)(x0 + ty + j) * DD + y0 + tx] = __float2half(t[tx][ty + j]);
}

__global__ void concat_bias(const float* bq, const float* bk, const float* bv, float* o)
{
    const int i = blockIdx.x * 256 + threadIdx.x;
    if (i < DD) o[i] = bq[i];
    else if (i < 2 * DD) o[i] = bk[i - DD];
    else if (i < ND) o[i] = bv[i - 2 * DD];
}

// V slice of QKVh (cols 2048..3071) -> Vt[b][d][s]
__global__ __launch_bounds__(256)
void transpose_v(const fp16* __restrict__ Vh, fp16* __restrict__ Vt)
{
    __shared__ fp16 t[32][33];
    const int tx = threadIdx.x, ty = threadIdx.y;
    const int d0 = blockIdx.x * 32, s0 = blockIdx.y * 32;
    const size_t rowOff = (size_t)blockIdx.z * SS;
    #pragma unroll
    for (int j = 0; j < 32; j += 8)
        t[ty + j][tx] = Vh[(rowOff + s0 + ty + j) * ND + 2 * DD + d0 + tx];
    __syncthreads();
    const size_t bo = (size_t)blockIdx.z * DD * SS;
    #pragma unroll
    for (int j = 0; j < 32; j += 8)
        Vt[bo + (size_t)(d0 + ty + j) * SS + s0 + tx] = t[tx][ty + j];
}

// 1 / rowsum of unnormalized P (fp16 in, fp32 out); one block per row
__global__ __launch_bounds__(256)
void rowsum_inv_kernel(const fp16* __restrict__ Pu, float* __restrict__ rsinv)
{
    __shared__ float red[256];
    const __half2* row = reinterpret_cast<const __half2*>(Pu + (size_t)blockIdx.x * SS);
    const int tid = threadIdx.x;
    float sum = 0.f;
    #pragma unroll
    for (int i = 0; i < 4; ++i) {
        const float2 p = __half22float2(row[tid + 256 * i]);
        sum += p.x + p.y;
    }
    red[tid] = sum; __syncthreads();
    #pragma unroll
    for (int s = 128; s > 0; s >>= 1) { if (tid < s) red[tid] += red[tid + s]; __syncthreads(); }
    if (tid == 0) rsinv[blockIdx.x] = __frcp_rn(red[0]);
}

// ---------------- launch ----------------
extern "C" void kernel_launch(void* const* d_in, const int* in_sizes, int n_in,
                              void* d_out, int out_size)
{
    const float* x  = (const float*)d_in[0];
    const float* Wq = (const float*)d_in[1];
    const float* bq = (const float*)d_in[2];
    const float* Wk = (const float*)d_in[3];
    const float* bk = (const float*)d_in[4];
    const float* Wv = (const float*)d_in[5];
    const float* bv = (const float*)d_in[6];
    float* out = (float*)d_out;

    fp16 *xh, *Wt, *QKVh, *Vt, *Pu;
    float *bias, *rsinv;
    cudaGetSymbolAddress((void**)&xh, g_xh);
    cudaGetSymbolAddress((void**)&Wt, g_Wt);
    cudaGetSymbolAddress((void**)&QKVh, g_QKVh);
    cudaGetSymbolAddress((void**)&Vt, g_Vt);
    cudaGetSymbolAddress((void**)&Pu, g_Pu);
    cudaGetSymbolAddress((void**)&bias, g_bias);
    cudaGetSymbolAddress((void**)&rsinv, g_rsinv);

    cudaFuncSetAttribute(tc_gemm<1, true>,  cudaFuncAttributeMaxDynamicSharedMemorySize, SMEM_TOTAL);
    cudaFuncSetAttribute(tc_gemm<2, false>, cudaFuncAttributeMaxDynamicSharedMemorySize, SMEM_TOTAL);
    cudaFuncSetAttribute(tc_gemm<3, false>, cudaFuncAttributeMaxDynamicSharedMemorySize, SMEM_TOTAL);

    const long long sQK = (long long)SS * ND;
    const long long sS  = (long long)SS * SS;

    // prep: 3 launches
    round_x_kernel<<<(BB * SS * DD / 4 + 255) / 256, 256>>>((const float4*)x, xh, BB * SS * DD / 4);
    transpose_round_w_all<<<dim3(DD / 32, DD / 32, 3), dim3(32, 8)>>>(Wq, Wk, Wv, Wt);
    concat_bias<<<(ND + 255) / 256, 256>>>(bq, bk, bv, bias);

    // merged QKV projection [16384,3072], fp16 out
    dim3 g1(ND / 128, BB * SS / 128, 1);                 // (24, 128)
    tc_gemm<1, true><<<g1, 256, SMEM_TOTAL>>>(xh, Wt, bias, nullptr, nullptr, QKVh,
                                              DD, DD, DD, 0, 0, 0, ND, 1.0f);

    // V -> Vt [b][d][s]
    transpose_v<<<dim3(DD / 32, SS / 32, BB), dim3(32, 8)>>>(QKVh, Vt);

    // Pu = exp((Q K^T)/32), fp16 out — fused softmax numerator
    dim3 g2(SS / 128, SS / 128, BB);                     // (16, 16, 8)
    tc_gemm<2, false><<<g2, 256, SMEM_TOTAL>>>(QKVh, QKVh + DD, nullptr, nullptr,
                                               nullptr, Pu,
                                               DD, ND, ND, sQK, sQK, sS, SS, 0.03125f);

    // rsinv = 1 / rowsum(Pu)
    rowsum_inv_kernel<<<BB * SS, 256>>>(Pu, rsinv);

    // out = (Pu V) * rsinv
    dim3 g3(DD / 128, SS / 128, BB);                     // (8, 16, 8)
    tc_gemm<3, false><<<g3, 256, SMEM_TOTAL>>>(Pu, Vt, nullptr, rsinv,
                                               out, nullptr,
                                               SS, SS, SS, sS, (long long)DD * SS,
                                               (long long)SS * DD, DD, 1.0f);
}

// round 14
// speedup vs baseline: 2.8394x; 1.0155x over previous
#include <cuda_runtime.h>
#include <cuda_fp16.h>
#include <cstdint>
#include <cstddef>

#define BB 8
#define SS 2048
#define DD 1024
#define ND 3072   // merged QKV output width

typedef __half fp16;

// ---------------- scratch ----------------
__device__ fp16 g_xh[(size_t)BB * SS * DD];      // x rounded to fp16
__device__ fp16 g_Wt[(size_t)ND * DD];           // [3072][1024] K-major, rounded fp16
__device__ float g_bias[ND];
__device__ fp16 g_QKVh[(size_t)BB * SS * ND];    // [16384][3072]
__device__ fp16 g_Vt[(size_t)BB * DD * SS];      // [b][d][s]
__device__ fp16 g_Pu[(size_t)BB * SS * SS];      // unnormalized exp(scores), fp16
__device__ float g_rsinv[(size_t)BB * SS];       // 1 / rowsum(exp(scores))

// ---------------- PTX helpers ----------------
__device__ __forceinline__ uint32_t smem_u32(const void* p) {
    uint32_t a;
    asm("{ .reg .u64 t; cvta.to.shared.u64 t, %1; cvt.u32.u64 %0, t; }" : "=r"(a) : "l"(p));
    return a;
}
__device__ __forceinline__ void cp16(uint32_t s, const void* g) {
    asm volatile("cp.async.cg.shared.global [%0], [%1], 16;\n" :: "r"(s), "l"(g));
}
__device__ __forceinline__ void cp_commit() { asm volatile("cp.async.commit_group;\n" ::: "memory"); }
template <int N> __device__ __forceinline__ void cp_wait() {
    asm volatile("cp.async.wait_group %0;\n" :: "n"(N) : "memory");
}
__device__ __forceinline__ void ldsm_x4(uint32_t& r0, uint32_t& r1, uint32_t& r2, uint32_t& r3, uint32_t a) {
    asm volatile("ldmatrix.sync.aligned.m8n8.x4.shared.b16 {%0,%1,%2,%3}, [%4];"
                 : "=r"(r0), "=r"(r1), "=r"(r2), "=r"(r3) : "r"(a));
}
__device__ __forceinline__ void mma16816(float* d,
                                         uint32_t a0, uint32_t a1, uint32_t a2, uint32_t a3,
                                         uint32_t b0, uint32_t b1) {
    asm volatile("mma.sync.aligned.m16n8k16.row.col.f32.f16.f16.f32 "
                 "{%0,%1,%2,%3}, {%4,%5,%6,%7}, {%8,%9}, {%0,%1,%2,%3};"
                 : "+f"(d[0]), "+f"(d[1]), "+f"(d[2]), "+f"(d[3])
                 : "r"(a0), "r"(a1), "r"(a2), "r"(a3), "r"(b0), "r"(b1));
}

#define SW128(o) ((o) ^ (((o) >> 3) & 0x70))

// smem stage: A (16K) + B (16K) = 32K; 3 stages = 96K; 2 CTAs/SM
static constexpr int S_A = 0, S_B = 16384;
static constexpr int STAGE = 32768;
static constexpr int STAGES = 3;
static constexpr int SMEM_TOTAL = STAGES * STAGE;   // 98304

// ---------------- 1-pass fp16 mma.sync GEMM, CTA 128x128, 256 thr, warp 64x32 ----------------
// Fragment-double-buffered across k-steps; single barrier per K-chunk.
// EPI: 1 = fp16 out (+bias)        [QKV projection]
//      2 = fp16 exp(scale*acc) out [scores -> unnormalized P]
//      3 = fp32 out * rsinv[row]   [PV with deferred softmax normalization]
template <int EPI, bool HASB>
__global__ __launch_bounds__(256, 2)
void tc_gemm(const fp16* __restrict__ A_, const fp16* __restrict__ B_,
             const float* __restrict__ bias, const float* __restrict__ rs,
             float* __restrict__ Co, fp16* __restrict__ Coh,
             int Kd, int lda, int ldb,
             long long sA, long long sB, long long sC, int ldo, float scale)
{
    extern __shared__ char smem[];
    const uint32_t su = smem_u32(smem);
    const int tid = threadIdx.x, lane = tid & 31, wid = tid >> 5;
    const int wm = wid >> 2, wn = wid & 3;           // 2(m) x 4(n), warp tile 64x32
    const int rowBase = blockIdx.y * 128, colBase = blockIdx.x * 128;

    A_ += (long long)blockIdx.z * sA;
    B_ += (long long)blockIdx.z * sB;
    if (EPI == 3) { Co += (long long)blockIdx.z * sC; rs += (long long)blockIdx.z * SS; }
    else          Coh += (long long)blockIdx.z * sC;

    float acc[16][4] = {};                            // [im*4+in][4]

    const int NC = Kd >> 6;

    auto load_stage = [&](int s, int k0) {
        const uint32_t base = su + s * STAGE;
        #pragma unroll
        for (int j = 0; j < 4; ++j) {                 // A: 128 rows x 64 fp16
            const int idx = tid + j * 256, r = idx >> 3, cu = idx & 7;
            const size_t go = (size_t)(rowBase + r) * lda + k0 + cu * 8;
            const uint32_t so = SW128((uint32_t)(r * 128 + cu * 16));
            cp16(base + S_A + so, A_ + go);
        }
        #pragma unroll
        for (int j = 0; j < 4; ++j) {                 // B: 128 rows x 64 fp16
            const int idx = tid + j * 256, r = idx >> 3, cu = idx & 7;
            const size_t go = (size_t)(colBase + r) * ldb + k0 + cu * 8;
            const uint32_t so = SW128((uint32_t)(r * 128 + cu * 16));
            cp16(base + S_B + so, B_ + go);
        }
        cp_commit();
    };

    load_stage(0, 0);
    load_stage(1, 64);

    const uint32_t sw   = (lane & 7) << 4;
    const uint32_t arow = (lane & 7) + (lane & 8);
    const uint32_t koff = (lane & 16);

    uint32_t ah[2][4][4], bh[2][2][4];                // double-buffered fragments

    auto ld_frags = [&](int buf, uint32_t base, int ks) {
        #pragma unroll
        for (int im = 0; im < 4; ++im) {
            const uint32_t off = (wm * 64 + im * 16 + arow) * 128 + ks * 32 + koff;
            ldsm_x4(ah[buf][im][0], ah[buf][im][1], ah[buf][im][2], ah[buf][im][3],
                    (base + S_A + off) ^ sw);
        }
        #pragma unroll
        for (int ip = 0; ip < 2; ++ip) {
            const uint32_t off = (wn * 32 + ip * 16 + arow) * 128 + ks * 32 + koff;
            ldsm_x4(bh[buf][ip][0], bh[buf][ip][1], bh[buf][ip][2], bh[buf][ip][3],
                    (base + S_B + off) ^ sw);
        }
    };

    for (int c = 0; c < NC; ++c) {
        cp_wait<1>();
        __syncthreads();                              // single barrier per chunk
        if (c + 2 < NC) load_stage((c + 2) % STAGES, (c + 2) << 6);
        else            cp_commit();

        const uint32_t base = su + (c % STAGES) * STAGE;
        ld_frags(0, base, 0);                         // prefetch ks=0
        #pragma unroll
        for (int ks = 0; ks < 4; ++ks) {
            const int cur = ks & 1, nxt = cur ^ 1;
            if (ks < 3) ld_frags(nxt, base, ks + 1);  // prefetch next ks before MMAs
            #pragma unroll
            for (int im = 0; im < 4; ++im)
                #pragma unroll
                for (int in = 0; in < 4; ++in) {
                    float* d = acc[im * 4 + in];
                    const int ip = in >> 1, sb = in & 1;
                    mma16816(d, ah[cur][im][0], ah[cur][im][1], ah[cur][im][2], ah[cur][im][3],
                             bh[cur][ip][sb], bh[cur][ip][2 + sb]);
                }
        }
    }

    // ---------------- epilogue ----------------
    #pragma unroll
    for (int im = 0; im < 4; ++im) {
        #pragma unroll
        for (int in = 0; in < 4; ++in) {
            const float* d = acc[im * 4 + in];
            const int row0 = rowBase + wm * 64 + im * 16 + (lane >> 2);
            const int col0 = colBase + wn * 32 + in * 8 + 2 * (lane & 3);
            #pragma unroll
            for (int h = 0; h < 2; ++h) {
                const int row = row0 + h * 8;
                float v0 = d[2 * h + 0], v1 = d[2 * h + 1];
                if (HASB) { v0 += bias[col0]; v1 += bias[col0 + 1]; }
                v0 *= scale; v1 *= scale;
                if (EPI == 1) {
                    __half2 H; H.x = __float2half(v0); H.y = __float2half(v1);
                    *reinterpret_cast<__half2*>(Coh + (size_t)row * ldo + col0) = H;
                } else if (EPI == 2) {
                    __half2 H;
                    H.x = __float2half(__expf(v0));
                    H.y = __float2half(__expf(v1));
                    *reinterpret_cast<__half2*>(Coh + (size_t)row * ldo + col0) = H;
                } else {
                    const float r = rs[row];
                    float2 f2; f2.x = v0 * r; f2.y = v1 * r;
                    *reinterpret_cast<float2*>(Co + (size_t)row * ldo + col0) = f2;
                }
            }
        }
    }
}

// ---------------- aux kernels ----------------
__global__ __launch_bounds__(256)
void round_x_kernel(const float4* __restrict__ src, fp16* __restrict__ hi, int n4)
{
    const int i = blockIdx.x * 256 + threadIdx.x;
    if (i >= n4) return;
    const float4 v = src[i];
    __half2 H0; H0.x = __float2half(v.x); H0.y = __float2half(v.y);
    __half2 H1; H1.x = __float2half(v.z); H1.y = __float2half(v.w);
    reinterpret_cast<__half2*>(hi)[2 * i] = H0;
    reinterpret_cast<__half2*>(hi)[2 * i + 1] = H1;
}

// all three W [1024][1024] fp32 -> Wt sections [n][k] fp16 (z selects the matrix)
__global__ __launch_bounds__(256)
void transpose_round_w_all(const float* __restrict__ Wq, const float* __restrict__ Wk,
                           const float* __restrict__ Wv, fp16* __restrict__ T)
{
    __shared__ float t[32][33];
    const float* W = (blockIdx.z == 0) ? Wq : (blockIdx.z == 1) ? Wk : Wv;
    fp16* Td = T + (size_t)blockIdx.z * DD * DD;
    const int tx = threadIdx.x, ty = threadIdx.y;
    const int x0 = blockIdx.x * 32, y0 = blockIdx.y * 32;
    #pragma unroll
    for (int j = 0; j < 32; j += 8)
        t[ty + j][tx] = W[(size_t)(y0 + ty + j) * DD + x0 + tx];
    __syncthreads();
    #pragma unroll
    for (int j = 0; j < 32; j += 8)
        Td[(size_t)(x0 + ty + j) * DD + y0 + tx] = __float2half(t[tx][ty + j]);
}

__global__ void concat_bias(const float* bq, const float* bk, const float* bv, float* o)
{
    const int i = blockIdx.x * 256 + threadIdx.x;
    if (i < DD) o[i] = bq[i];
    else if (i < 2 * DD) o[i] = bk[i - DD];
    else if (i < ND) o[i] = bv[i - 2 * DD];
}

// V slice of QKVh (cols 2048..3071) -> Vt[b][d][s]
__global__ __launch_bounds__(256)
void transpose_v(const fp16* __restrict__ Vh, fp16* __restrict__ Vt)
{
    __shared__ fp16 t[32][33];
    const int tx = threadIdx.x, ty = threadIdx.y;
    const int d0 = blockIdx.x * 32, s0 = blockIdx.y * 32;
    const size_t rowOff = (size_t)blockIdx.z * SS;
    #pragma unroll
    for (int j = 0; j < 32; j += 8)
        t[ty + j][tx] = Vh[(rowOff + s0 + ty + j) * ND + 2 * DD + d0 + tx];
    __syncthreads();
    const size_t bo = (size_t)blockIdx.z * DD * SS;
    #pragma unroll
    for (int j = 0; j < 32; j += 8)
        Vt[bo + (size_t)(d0 + ty + j) * SS + s0 + tx] = t[tx][ty + j];
}

// 1 / rowsum of unnormalized P (fp16 in, fp32 out); one block per row
__global__ __launch_bounds__(256)
void rowsum_inv_kernel(const fp16* __restrict__ Pu, float* __restrict__ rsinv)
{
    __shared__ float red[256];
    const __half2* row = reinterpret_cast<const __half2*>(Pu + (size_t)blockIdx.x * SS);
    const int tid = threadIdx.x;
    float sum = 0.f;
    #pragma unroll
    for (int i = 0; i < 4; ++i) {
        const float2 p = __half22float2(row[tid + 256 * i]);
        sum += p.x + p.y;
    }
    red[tid] = sum; __syncthreads();
    #pragma unroll
    for (int s = 128; s > 0; s >>= 1) { if (tid < s) red[tid] += red[tid + s]; __syncthreads(); }
    if (tid == 0) rsinv[blockIdx.x] = __frcp_rn(red[0]);
}

// ---------------- launch ----------------
extern "C" void kernel_launch(void* const* d_in, const int* in_sizes, int n_in,
                              void* d_out, int out_size)
{
    const float* x  = (const float*)d_in[0];
    const float* Wq = (const float*)d_in[1];
    const float* bq = (const float*)d_in[2];
    const float* Wk = (const float*)d_in[3];
    const float* bk = (const float*)d_in[4];
    const float* Wv = (const float*)d_in[5];
    const float* bv = (const float*)d_in[6];
    float* out = (float*)d_out;

    fp16 *xh, *Wt, *QKVh, *Vt, *Pu;
    float *bias, *rsinv;
    cudaGetSymbolAddress((void**)&xh, g_xh);
    cudaGetSymbolAddress((void**)&Wt, g_Wt);
    cudaGetSymbolAddress((void**)&QKVh, g_QKVh);
    cudaGetSymbolAddress((void**)&Vt, g_Vt);
    cudaGetSymbolAddress((void**)&Pu, g_Pu);
    cudaGetSymbolAddress((void**)&bias, g_bias);
    cudaGetSymbolAddress((void**)&rsinv, g_rsinv);

    cudaFuncSetAttribute(tc_gemm<1, true>,  cudaFuncAttributeMaxDynamicSharedMemorySize, SMEM_TOTAL);
    cudaFuncSetAttribute(tc_gemm<2, false>, cudaFuncAttributeMaxDynamicSharedMemorySize, SMEM_TOTAL);
    cudaFuncSetAttribute(tc_gemm<3, false>, cudaFuncAttributeMaxDynamicSharedMemorySize, SMEM_TOTAL);

    const long long sQK = (long long)SS * ND;
    const long long sS  = (long long)SS * SS;

    // prep: 3 launches
    round_x_kernel<<<(BB * SS * DD / 4 + 255) / 256, 256>>>((const float4*)x, xh, BB * SS * DD / 4);
    transpose_round_w_all<<<dim3(DD / 32, DD / 32, 3), dim3(32, 8)>>>(Wq, Wk, Wv, Wt);
    concat_bias<<<(ND + 255) / 256, 256>>>(bq, bk, bv, bias);

    // merged QKV projection [16384,3072], fp16 out   (ncu -s 5 lands here)
    dim3 g1(ND / 128, BB * SS / 128, 1);                 // (24, 128)
    tc_gemm<1, true><<<g1, 256, SMEM_TOTAL>>>(xh, Wt, bias, nullptr, nullptr, QKVh,
                                              DD, DD, DD, 0, 0, 0, ND, 1.0f);

    // V -> Vt [b][d][s]
    transpose_v<<<dim3(DD / 32, SS / 32, BB), dim3(32, 8)>>>(QKVh, Vt);

    // Pu = exp((Q K^T)/32), fp16 out — fused softmax numerator
    dim3 g2(SS / 128, SS / 128, BB);                     // (16, 16, 8)
    tc_gemm<2, false><<<g2, 256, SMEM_TOTAL>>>(QKVh, QKVh + DD, nullptr, nullptr,
                                               nullptr, Pu,
                                               DD, ND, ND, sQK, sQK, sS, SS, 0.03125f);

    // rsinv = 1 / rowsum(Pu)
    rowsum_inv_kernel<<<BB * SS, 256>>>(Pu, rsinv);

    // out = (Pu V) * rsinv
    dim3 g3(DD / 128, SS / 128, BB);                     // (8, 16, 8)
    tc_gemm<3, false><<<g3, 256, SMEM_TOTAL>>>(Pu, Vt, nullptr, rsinv,
                                               out, nullptr,
                                               SS, SS, SS, sS, (long long)DD * SS,
                                               (long long)SS * DD, DD, 1.0f);
}